// round 11
// baseline (speedup 1.0000x reference)
#include <cuda_runtime.h>
#include <math.h>
#include <stdint.h>

// Problem sizes (fixed by the reference)
#define BB 8
#define LL 2048
#define DD 512
#define MT (BB*LL)          // 16384 rows
#define SZ ((long long)MT*DD)

// ---------------- scratch (device globals; no allocation allowed) ----------------
__device__ float g_xct[MT*DD];       // conv output, tf32-rounded (GEMM A + EPI2 aux)
__device__ float g_h1[2*MT*DD];      // tf32 gelu(xc@{eta,alpha}w1); later gemm<3> output
__device__ float g_hm[MT*DD];        // raw q-gemm out, tf32-rounded (A of gemm<3>, aux of gemm<4>)
__device__ float g_accum[MT + 2*LL]; // [0:MT) hs rowsums, [MT:MT+LL) eta sum, [MT+LL:) alpha sum
__device__ float g_ps[2*LL];         // [0:LL) p,  [LL:2LL) s
__device__ float g_qsum[MT];         // s_r * rowsum(hm_r)
__device__ float g_rs[MT];           // per-row l2norm scale s_r
__device__ float g_wt[7*DD*DD];      // transposed+tf32-rounded weights

__device__ __forceinline__ float gelu_exact(float x) {
    return 0.5f * x * (1.0f + erff(x * 0.70710678118654752f));
}
__device__ __forceinline__ float sigm(float x) {
    return 1.0f / (1.0f + expf(-x));
}
__device__ __forceinline__ uint32_t tf32_bits(float x) {
    uint32_t u; asm("cvt.rna.tf32.f32 %0, %1;" : "=r"(u) : "f"(x)); return u;
}
__device__ __forceinline__ float tf32_round(float x) {
    return __uint_as_float(tf32_bits(x));
}
__device__ __forceinline__ uint32_t smem_u32(const void* p) {
    uint32_t a;
    asm("{ .reg .u64 t; cvta.to.shared.u64 t, %1; cvt.u32.u64 %0, t; }" : "=r"(a) : "l"(p));
    return a;
}

// ---------------- zero accumulators ----------------
__global__ void zero_kernel(float* a, int n) {
    int i = blockIdx.x * blockDim.x + threadIdx.x;
    if (i < n) a[i] = 0.0f;
}

// ---------------- prep weights: transpose (or copy) + tf32 round ----------------
// slots: 0 eta_w1^T, 1 alpha_w1^T, 2 eta_w2^T, 3 alpha_w2^T, 4 q_w (copy), 5 mem_w1^T, 6 mem_w2^T
__global__ void prep_weights(const float* __restrict__ ew1, const float* __restrict__ aw1,
                             const float* __restrict__ ew2, const float* __restrict__ aw2,
                             const float* __restrict__ qw,  const float* __restrict__ mw1,
                             const float* __restrict__ mw2, float* __restrict__ wt) {
    __shared__ float tile[32][33];
    int zi = blockIdx.z;
    const float* src; bool tr = true;
    switch (zi) {
        case 0: src = ew1; break;
        case 1: src = aw1; break;
        case 2: src = ew2; break;
        case 3: src = aw2; break;
        case 4: src = qw; tr = false; break;
        case 5: src = mw1; break;
        default: src = mw2; break;
    }
    float* dst = wt + (long long)zi * DD * DD;
    int bx = blockIdx.x * 32, by = blockIdx.y * 32;
    int tx = threadIdx.x, ty = threadIdx.y;  // (32, 8)
    if (tr) {
        #pragma unroll
        for (int i = 0; i < 32; i += 8)
            tile[ty + i][tx] = src[(long long)(by + ty + i) * DD + bx + tx];
        __syncthreads();
        #pragma unroll
        for (int i = 0; i < 32; i += 8)
            dst[(long long)(bx + ty + i) * DD + by + tx] = tf32_round(tile[tx][ty + i]);
    } else {
        #pragma unroll
        for (int i = 0; i < 32; i += 8)
            dst[(long long)(by + ty + i) * DD + bx + tx] =
                tf32_round(src[(long long)(by + ty + i) * DD + bx + tx]);
    }
}

// ---------------- causal depthwise conv (k=4, left pad 3) + bias -> tf32 ----------
__global__ void conv_kernel(const float* __restrict__ x, const float* __restrict__ w,
                            const float* __restrict__ bias, float* __restrict__ xct) {
    int idx = blockIdx.x * blockDim.x + threadIdx.x;
    if (idx >= MT * (DD/4)) return;
    int d4 = idx & 127;
    int r  = idx >> 7;
    int l  = r & (LL-1);
    int d  = d4 * 4;
    float4 out = *(const float4*)(bias + d);
    #pragma unroll
    for (int k = 0; k < 4; k++) {
        int li = l + k - 3;
        if (li >= 0) {
            float4 xv = *(const float4*)(x + (long long)(r + k - 3) * DD + d);
            out.x += xv.x * w[(d+0)*4 + k];
            out.y += xv.y * w[(d+1)*4 + k];
            out.z += xv.z * w[(d+2)*4 + k];
            out.w += xv.w * w[(d+3)*4 + k];
        }
    }
    float4 rt = { tf32_round(out.x), tf32_round(out.y), tf32_round(out.z), tf32_round(out.w) };
    *(float4*)(xct + (long long)r * DD + d) = rt;
}

// ---------------- row norms: s_r = 1/max(||hm_r||, eps), qsum_r = s_r*sum(hm_r) ----
__global__ void rownorm_kernel(const float* __restrict__ G, float* __restrict__ rs,
                               float* __restrict__ qsum) {
    int r = blockIdx.x;
    int t = threadIdx.x;   // 128
    float4 v = ((const float4*)(G + (long long)r * DD))[t];
    float ss = v.x*v.x + v.y*v.y + v.z*v.z + v.w*v.w;
    float sg = v.x + v.y + v.z + v.w;
    #pragma unroll
    for (int o = 16; o > 0; o >>= 1) {
        ss += __shfl_down_sync(0xffffffffu, ss, o);
        sg += __shfl_down_sync(0xffffffffu, sg, o);
    }
    __shared__ float sh_ss[4], sh_sg[4];
    int w = t >> 5;
    if ((t & 31) == 0) { sh_ss[w] = ss; sh_sg[w] = sg; }
    __syncthreads();
    if (t == 0) {
        float S  = sh_ss[0] + sh_ss[1] + sh_ss[2] + sh_ss[3];
        float Gs = sh_sg[0] + sh_sg[1] + sh_sg[2] + sh_sg[3];
        float scale = 1.0f / fmaxf(sqrtf(S), 1e-12f);
        rs[r]   = scale;
        qsum[r] = Gs * scale;
    }
}

// ---------------- parallel affine scan for p_t, s_t ----------------
__global__ void scan_kernel(const float* __restrict__ red, float* __restrict__ PS) {
    __shared__ float Aa[2][LL];
    __shared__ float Bb[2][LL];
    const float inv = 1.0f / (float)(BB * DD);
    int t = threadIdx.x;  // 1024
    #pragma unroll
    for (int h = 0; h < 2; h++) {
        int e = t + h * 1024;
        Aa[0][e] = red[LL + e] * inv;        // alpha mean
        Bb[0][e] = -0.01f * red[e] * inv;    // -0.01 * eta mean
    }
    int cur = 0;
    for (int d = 1; d < LL; d <<= 1) {
        __syncthreads();
        #pragma unroll
        for (int h = 0; h < 2; h++) {
            int e = t + h * 1024;
            float A2 = Aa[cur][e], B2 = Bb[cur][e];
            if (e >= d) {
                float A1 = Aa[cur][e - d], B1 = Bb[cur][e - d];
                B2 = A2 * B1 + B2;
                A2 = A1 * A2;
            }
            Aa[cur ^ 1][e] = A2;
            Bb[cur ^ 1][e] = B2;
        }
        cur ^= 1;
    }
    __syncthreads();
    #pragma unroll
    for (int h = 0; h < 2; h++) {
        int e = t + h * 1024;
        PS[e]      = (e == 0) ? 1.0f : Aa[cur][e - 1];
        PS[LL + e] = (e == 0) ? 0.0f : Bb[cur][e - 1];
    }
}

// ---------------- tf32 mma.sync GEMM (R4 core), cp.async 3-stage pipeline ----------
// All operands pre-rounded tf32 in gmem, row-major K-contiguous. CTA 128x128, BK=32.
// EPI 0: C = tf32(acc)                                  [raw q-gemm]
// EPI 1: C = tf32(gelu(acc))
// EPI 2: no store; atomicAdd red[(r&2047)] += sum_cols sigmoid(aux[r,c]+acc)
// EPI 3: h = gelu(P[l]*RS[r]*acc + S[l]*vin[r]); C = tf32(h); atomicAdd red0[r] += sum h
// EPI 4: C = RS[r]*aux[r,c] + P[l]*acc + S[l]*vin[r]
#define SW 36           // smem row stride (words): conflict-free frag gathers
#define STG_WORDS (128*SW)          // 4608 words = 18432 B per matrix-stage
#define SMEM_GB (6*STG_WORDS*4)     // 3 stages x (A+B) = 110592 B

template<int EPI>
__global__ __launch_bounds__(256, 2)
void gemm_mma(const float* __restrict__ A, long long Astride,
              const float* __restrict__ Bt0, const float* __restrict__ Bt1,
              float* C0, float* C1,
              const float* __restrict__ aux,
              const float* __restrict__ P, const float* __restrict__ S,
              const float* __restrict__ vin,
              const float* __restrict__ RS,
              float* red0, float* red1) {
    extern __shared__ uint32_t smemBuf[];
    const uint32_t sbase = smem_u32(smemBuf);

    const int tid  = threadIdx.x;
    const int lane = tid & 31, warp = tid >> 5;
    const int wm = warp >> 2, wn = warp & 3;       // 2 x 4 warp grid
    const int qr = lane >> 2, qk = lane & 3;
    const int rowBase = blockIdx.y * 128;
    const int colBase = blockIdx.x * 128;
    const int z = blockIdx.z;
    const float* Ab = A + (long long)z * Astride;
    const float* Bt = z ? Bt1 : Bt0;
    float* C        = z ? C1 : C0;

    float acc[4][4][4];
    #pragma unroll
    for (int mf = 0; mf < 4; mf++)
        #pragma unroll
        for (int nf = 0; nf < 4; nf++)
            #pragma unroll
            for (int i = 0; i < 4; i++) acc[mf][nf][i] = 0.0f;

    // per-thread load coords (4 x 16B each for A and B per BK=32 chunk)
    const int lr = tid >> 3;
    const int lc = (tid & 7) * 4;

    auto issue = [&](int kc, int s) {
        const int k0 = kc * 32;
        const uint32_t abase = sbase + s * (STG_WORDS * 4);
        const uint32_t bbase = sbase + (3 + s) * (STG_WORDS * 4);
        #pragma unroll
        for (int i = 0; i < 4; i++) {
            int row = lr + i * 32;
            const float* ga = Ab + (long long)(rowBase + row) * DD + k0 + lc;
            const float* gb = Bt + (long long)(colBase + row) * DD + k0 + lc;
            uint32_t da = abase + (row * SW + lc) * 4;
            uint32_t db = bbase + (row * SW + lc) * 4;
            asm volatile("cp.async.cg.shared.global [%0], [%1], 16;"
                :: "r"(da), "l"(__cvta_generic_to_global(ga)));
            asm volatile("cp.async.cg.shared.global [%0], [%1], 16;"
                :: "r"(db), "l"(__cvta_generic_to_global(gb)));
        }
        asm volatile("cp.async.commit_group;" ::: "memory");
    };

    issue(0, 0);
    issue(1, 1);

    int s = 0;
    for (int kc = 0; kc < 16; kc++) {
        // kc<15: groups {kc, kc+1} pending -> wait_group 1 retires kc.
        // kc==15: only group 15 pending -> wait_group 1 would be a no-op (race).
        if (kc < 15) { asm volatile("cp.async.wait_group 1;" ::: "memory"); }
        else         { asm volatile("cp.async.wait_group 0;" ::: "memory"); }
        __syncthreads();
        const uint32_t* As = smemBuf + s * STG_WORDS;
        const uint32_t* Bs = smemBuf + (3 + s) * STG_WORDS;

        #pragma unroll
        for (int ks = 0; ks < 4; ks++) {
            uint32_t a[4][4], b[4][2];
            const uint32_t* ap = &As[(wm * 64 + qr) * SW + ks * 8 + qk];
            #pragma unroll
            for (int mf = 0; mf < 4; mf++) {
                a[mf][0] = ap[(mf * 16    ) * SW];
                a[mf][1] = ap[(mf * 16 + 8) * SW];
                a[mf][2] = ap[(mf * 16    ) * SW + 4];
                a[mf][3] = ap[(mf * 16 + 8) * SW + 4];
            }
            const uint32_t* bp = &Bs[(wn * 32 + qr) * SW + ks * 8 + qk];
            #pragma unroll
            for (int nf = 0; nf < 4; nf++) {
                b[nf][0] = bp[nf * 8 * SW];
                b[nf][1] = bp[nf * 8 * SW + 4];
            }
            #pragma unroll
            for (int mf = 0; mf < 4; mf++)
                #pragma unroll
                for (int nf = 0; nf < 4; nf++)
                    asm volatile(
                        "mma.sync.aligned.m16n8k8.row.col.f32.tf32.tf32.f32 "
                        "{%0,%1,%2,%3}, {%4,%5,%6,%7}, {%8,%9}, {%0,%1,%2,%3};"
                        : "+f"(acc[mf][nf][0]), "+f"(acc[mf][nf][1]),
                          "+f"(acc[mf][nf][2]), "+f"(acc[mf][nf][3])
                        : "r"(a[mf][0]), "r"(a[mf][1]), "r"(a[mf][2]), "r"(a[mf][3]),
                          "r"(b[nf][0]), "r"(b[nf][1]));
        }
        if (kc < 14) issue(kc + 2, (s + 2) % 3);
        s = (s + 1) % 3;
    }

    // ---- epilogue ----
    float* red = (EPI == 2) ? (z ? red1 : red0) : red0;
    const int cBase = colBase + wn * 32 + 2 * qk;

    #pragma unroll
    for (int mf = 0; mf < 4; mf++) {
        #pragma unroll
        for (int half_ = 0; half_ < 2; half_++) {
            int r = rowBase + wm * 64 + mf * 16 + qr + half_ * 8;
            int l = r & (LL - 1);
            int ci = half_ * 2;
            float part = 0.0f;
            float pl = 0.f, sl = 0.f, vv = 0.f, rsv = 0.f;
            if (EPI == 3 || EPI == 4) { pl = P[l]; sl = S[l]; vv = vin[r]; rsv = RS[r]; }
            long long ro = (long long)r * DD;

            #pragma unroll
            for (int nf = 0; nf < 4; nf++) {
                float v0 = acc[mf][nf][ci], v1 = acc[mf][nf][ci + 1];
                long long off = ro + cBase + nf * 8;
                if (EPI == 0) {
                    float2 o = { tf32_round(v0), tf32_round(v1) };
                    *(float2*)(C + off) = o;
                } else if (EPI == 1) {
                    float2 o = { tf32_round(gelu_exact(v0)), tf32_round(gelu_exact(v1)) };
                    *(float2*)(C + off) = o;
                } else if (EPI == 2) {
                    float2 a2 = *(const float2*)(aux + off);
                    part += sigm(a2.x + v0) + sigm(a2.y + v1);
                } else if (EPI == 3) {
                    float h0 = gelu_exact(pl * (rsv * v0) + sl * vv);
                    float h1 = gelu_exact(pl * (rsv * v1) + sl * vv);
                    part += h0 + h1;
                    float2 o = { tf32_round(h0), tf32_round(h1) };
                    *(float2*)(C + off) = o;
                } else if (EPI == 4) {
                    float2 a2 = *(const float2*)(aux + off);
                    float2 o = { rsv * a2.x + pl * v0 + sl * vv,
                                 rsv * a2.y + pl * v1 + sl * vv };
                    *(float2*)(C + off) = o;
                }
            }
            if (EPI == 2 || EPI == 3) {
                part += __shfl_xor_sync(0xffffffffu, part, 1);
                part += __shfl_xor_sync(0xffffffffu, part, 2);
                if (qk == 0) {
                    if (EPI == 2) atomicAdd(&red[l], part);
                    else          atomicAdd(&red[r], part);
                }
            }
        }
    }
}

// ---------------- launcher ----------------
extern "C" void kernel_launch(void* const* d_in, const int* in_sizes, int n_in,
                              void* d_out, int out_size) {
    const float* x        = (const float*)d_in[0];
    const float* conv_w   = (const float*)d_in[1];
    const float* conv_b   = (const float*)d_in[2];
    const float* q_w      = (const float*)d_in[3];
    const float* mem_w1   = (const float*)d_in[4];
    const float* mem_w2   = (const float*)d_in[5];
    const float* eta_w1   = (const float*)d_in[6];
    const float* eta_w2   = (const float*)d_in[7];
    const float* alpha_w1 = (const float*)d_in[8];
    const float* alpha_w2 = (const float*)d_in[9];
    float* out = (float*)d_out;

    float *xct, *h1, *hm, *accum, *ps, *qsum, *rs, *wt;
    cudaGetSymbolAddress((void**)&xct,   g_xct);
    cudaGetSymbolAddress((void**)&h1,    g_h1);
    cudaGetSymbolAddress((void**)&hm,    g_hm);
    cudaGetSymbolAddress((void**)&accum, g_accum);
    cudaGetSymbolAddress((void**)&ps,    g_ps);
    cudaGetSymbolAddress((void**)&qsum,  g_qsum);
    cudaGetSymbolAddress((void**)&rs,    g_rs);
    cudaGetSymbolAddress((void**)&wt,    g_wt);

    float* hs        = accum;
    float* eta_sum   = accum + MT;
    float* alpha_sum = accum + MT + LL;
    float* Pp = ps;
    float* Ss = ps + LL;

    static bool attr_done = false;
    if (!attr_done) {
        cudaFuncSetAttribute(gemm_mma<0>, cudaFuncAttributeMaxDynamicSharedMemorySize, SMEM_GB);
        cudaFuncSetAttribute(gemm_mma<1>, cudaFuncAttributeMaxDynamicSharedMemorySize, SMEM_GB);
        cudaFuncSetAttribute(gemm_mma<2>, cudaFuncAttributeMaxDynamicSharedMemorySize, SMEM_GB);
        cudaFuncSetAttribute(gemm_mma<3>, cudaFuncAttributeMaxDynamicSharedMemorySize, SMEM_GB);
        cudaFuncSetAttribute(gemm_mma<4>, cudaFuncAttributeMaxDynamicSharedMemorySize, SMEM_GB);
        attr_done = true;
    }

    // 0) zero atomic accumulators
    {
        int n = MT + 2 * LL;
        zero_kernel<<<(n + 255) / 256, 256>>>(accum, n);
    }
    // 0b) weights -> transposed + tf32
    prep_weights<<<dim3(16, 16, 7), dim3(32, 8)>>>(eta_w1, alpha_w1, eta_w2, alpha_w2,
                                                   q_w, mem_w1, mem_w2, wt);
    // 1) conv -> xct (tf32 only)
    conv_kernel<<<(MT * (DD/4) + 255) / 256, 256>>>(x, conv_w, conv_b, xct);

    dim3 grid2(DD / 128, MT / 128, 2);
    dim3 grid1(DD / 128, MT / 128, 1);
    float* wt0 = wt + 0LL * DD * DD;  // eta_w1^T
    float* wt1 = wt + 1LL * DD * DD;  // alpha_w1^T
    float* wt2 = wt + 2LL * DD * DD;  // eta_w2^T
    float* wt3 = wt + 3LL * DD * DD;  // alpha_w2^T
    float* wt4 = wt + 4LL * DD * DD;  // q_w
    float* wt5 = wt + 5LL * DD * DD;  // mem_w1^T
    float* wt6 = wt + 6LL * DD * DD;  // mem_w2^T

    // 2) batched xct @ {eta_w1, alpha_w1} -> tf32(gelu) -> h1[z]
    gemm_mma<1><<<grid2, 256, SMEM_GB>>>(xct, 0LL, wt0, wt1, h1, h1 + SZ,
                                         nullptr, nullptr, nullptr, nullptr, nullptr,
                                         nullptr, nullptr);
    // 3) batched h1[z] @ {eta_w2, alpha_w2} -> sigmoid(xct + .) -> per-l sums
    gemm_mma<2><<<grid2, 256, SMEM_GB>>>(h1, SZ, wt2, wt3, nullptr, nullptr,
                                         xct, nullptr, nullptr, nullptr, nullptr,
                                         eta_sum, alpha_sum);
    // 4) xct @ q_w^T -> hm (tf32-rounded raw q-gemm)
    gemm_mma<0><<<grid1, 256, SMEM_GB>>>(xct, 0LL, wt4, wt4, hm, hm,
                                         nullptr, nullptr, nullptr, nullptr, nullptr,
                                         nullptr, nullptr);
    // 5) row norms -> rs, qsum (reduction only)
    rownorm_kernel<<<MT, 128>>>(hm, rs, qsum);
    // 6) parallel affine scan -> p, s
    scan_kernel<<<1, 1024>>>(eta_sum, ps);
    // 7) hm @ mem_w1, epilogue folds l2norm scale: gelu(P*RS*acc + S*qsum) -> h1, hs
    gemm_mma<3><<<grid1, 256, SMEM_GB>>>(hm, 0LL, wt5, wt5, h1, h1,
                                         nullptr, Pp, Ss, qsum, rs,
                                         hs, nullptr);
    // 8) h1 @ mem_w2, final epilogue: out = RS*hm + P*acc + S*hs
    gemm_mma<4><<<grid1, 256, SMEM_GB>>>(h1, 0LL, wt6, wt6, out, out,
                                         hm, Pp, Ss, hs, rs,
                                         nullptr, nullptr);
}

// round 12
// speedup vs baseline: 1.5832x; 1.5832x over previous
#include <cuda_runtime.h>
#include <math.h>
#include <stdint.h>

// Problem sizes (fixed by the reference)
#define BB 8
#define LL 2048
#define DD 512
#define MT (BB*LL)          // 16384 rows
#define SZ ((long long)MT*DD)

// ---------------- scratch (device globals; no allocation allowed) ----------------
__device__ float g_xct[MT*DD];       // conv output, tf32-rounded (GEMM A + EPI2 aux)
__device__ float g_h1[2*MT*DD];      // tf32 gelu(xc@{eta,alpha}w1); later gemm<3> output
__device__ float g_hm[MT*DD];        // raw q-gemm out, tf32-rounded (A of gemm<3>, aux of gemm<4>)
__device__ float g_accum[MT + 2*LL]; // [0:MT) hs rowsums, [MT:MT+LL) eta sum, [MT+LL:) alpha sum
__device__ float g_ps[2*LL];         // [0:LL) p,  [LL:2LL) s
__device__ float g_qsum[MT];         // s_r * rowsum(hm_r)
__device__ float g_rs[MT];           // per-row l2norm scale s_r
__device__ float g_wt[7*DD*DD];      // transposed+tf32-rounded weights

__device__ __forceinline__ float gelu_exact(float x) {
    return 0.5f * x * (1.0f + erff(x * 0.70710678118654752f));
}
__device__ __forceinline__ float sigm(float x) {
    return 1.0f / (1.0f + expf(-x));
}
__device__ __forceinline__ uint32_t tf32_bits(float x) {
    uint32_t u; asm("cvt.rna.tf32.f32 %0, %1;" : "=r"(u) : "f"(x)); return u;
}
__device__ __forceinline__ float tf32_round(float x) {
    return __uint_as_float(tf32_bits(x));
}
__device__ __forceinline__ uint32_t smem_u32(const void* p) {
    uint32_t a;
    asm("{ .reg .u64 t; cvta.to.shared.u64 t, %1; cvt.u32.u64 %0, t; }" : "=r"(a) : "l"(p));
    return a;
}

// ---------------- zero accumulators ----------------
__global__ void zero_kernel(float* a, int n) {
    int i = blockIdx.x * blockDim.x + threadIdx.x;
    if (i < n) a[i] = 0.0f;
}

// ---------------- prep weights: transpose (or copy) + tf32 round ----------------
// slots: 0 eta_w1^T, 1 alpha_w1^T, 2 eta_w2^T, 3 alpha_w2^T, 4 q_w (copy), 5 mem_w1^T, 6 mem_w2^T
__global__ void prep_weights(const float* __restrict__ ew1, const float* __restrict__ aw1,
                             const float* __restrict__ ew2, const float* __restrict__ aw2,
                             const float* __restrict__ qw,  const float* __restrict__ mw1,
                             const float* __restrict__ mw2, float* __restrict__ wt) {
    __shared__ float tile[32][33];
    int zi = blockIdx.z;
    const float* src; bool tr = true;
    switch (zi) {
        case 0: src = ew1; break;
        case 1: src = aw1; break;
        case 2: src = ew2; break;
        case 3: src = aw2; break;
        case 4: src = qw; tr = false; break;
        case 5: src = mw1; break;
        default: src = mw2; break;
    }
    float* dst = wt + (long long)zi * DD * DD;
    int bx = blockIdx.x * 32, by = blockIdx.y * 32;
    int tx = threadIdx.x, ty = threadIdx.y;  // (32, 8)
    if (tr) {
        #pragma unroll
        for (int i = 0; i < 32; i += 8)
            tile[ty + i][tx] = src[(long long)(by + ty + i) * DD + bx + tx];
        __syncthreads();
        #pragma unroll
        for (int i = 0; i < 32; i += 8)
            dst[(long long)(bx + ty + i) * DD + by + tx] = tf32_round(tile[tx][ty + i]);
    } else {
        #pragma unroll
        for (int i = 0; i < 32; i += 8)
            dst[(long long)(by + ty + i) * DD + bx + tx] =
                tf32_round(src[(long long)(by + ty + i) * DD + bx + tx]);
    }
}

// ---------------- causal depthwise conv (k=4, left pad 3) + bias -> tf32 ----------
__global__ void conv_kernel(const float* __restrict__ x, const float* __restrict__ w,
                            const float* __restrict__ bias, float* __restrict__ xct) {
    int idx = blockIdx.x * blockDim.x + threadIdx.x;
    if (idx >= MT * (DD/4)) return;
    int d4 = idx & 127;
    int r  = idx >> 7;
    int l  = r & (LL-1);
    int d  = d4 * 4;
    float4 out = *(const float4*)(bias + d);
    #pragma unroll
    for (int k = 0; k < 4; k++) {
        int li = l + k - 3;
        if (li >= 0) {
            float4 xv = *(const float4*)(x + (long long)(r + k - 3) * DD + d);
            out.x += xv.x * w[(d+0)*4 + k];
            out.y += xv.y * w[(d+1)*4 + k];
            out.z += xv.z * w[(d+2)*4 + k];
            out.w += xv.w * w[(d+3)*4 + k];
        }
    }
    float4 rt = { tf32_round(out.x), tf32_round(out.y), tf32_round(out.z), tf32_round(out.w) };
    *(float4*)(xct + (long long)r * DD + d) = rt;
}

// ---------------- row norms: s_r = 1/max(||hm_r||, eps), qsum_r = s_r*sum(hm_r) ----
__global__ void rownorm_kernel(const float* __restrict__ G, float* __restrict__ rs,
                               float* __restrict__ qsum) {
    int r = blockIdx.x;
    int t = threadIdx.x;   // 128
    float4 v = ((const float4*)(G + (long long)r * DD))[t];
    float ss = v.x*v.x + v.y*v.y + v.z*v.z + v.w*v.w;
    float sg = v.x + v.y + v.z + v.w;
    #pragma unroll
    for (int o = 16; o > 0; o >>= 1) {
        ss += __shfl_down_sync(0xffffffffu, ss, o);
        sg += __shfl_down_sync(0xffffffffu, sg, o);
    }
    __shared__ float sh_ss[4], sh_sg[4];
    int w = t >> 5;
    if ((t & 31) == 0) { sh_ss[w] = ss; sh_sg[w] = sg; }
    __syncthreads();
    if (t == 0) {
        float S  = sh_ss[0] + sh_ss[1] + sh_ss[2] + sh_ss[3];
        float Gs = sh_sg[0] + sh_sg[1] + sh_sg[2] + sh_sg[3];
        float scale = 1.0f / fmaxf(sqrtf(S), 1e-12f);
        rs[r]   = scale;
        qsum[r] = Gs * scale;
    }
}

// ---------------- parallel affine scan for p_t, s_t ----------------
__global__ void scan_kernel(const float* __restrict__ red, float* __restrict__ PS) {
    __shared__ float Aa[2][LL];
    __shared__ float Bb[2][LL];
    const float inv = 1.0f / (float)(BB * DD);
    int t = threadIdx.x;  // 1024
    #pragma unroll
    for (int h = 0; h < 2; h++) {
        int e = t + h * 1024;
        Aa[0][e] = red[LL + e] * inv;        // alpha mean
        Bb[0][e] = -0.01f * red[e] * inv;    // -0.01 * eta mean
    }
    int cur = 0;
    for (int d = 1; d < LL; d <<= 1) {
        __syncthreads();
        #pragma unroll
        for (int h = 0; h < 2; h++) {
            int e = t + h * 1024;
            float A2 = Aa[cur][e], B2 = Bb[cur][e];
            if (e >= d) {
                float A1 = Aa[cur][e - d], B1 = Bb[cur][e - d];
                B2 = A2 * B1 + B2;
                A2 = A1 * A2;
            }
            Aa[cur ^ 1][e] = A2;
            Bb[cur ^ 1][e] = B2;
        }
        cur ^= 1;
    }
    __syncthreads();
    #pragma unroll
    for (int h = 0; h < 2; h++) {
        int e = t + h * 1024;
        PS[e]      = (e == 0) ? 1.0f : Aa[cur][e - 1];
        PS[LL + e] = (e == 0) ? 0.0f : Bb[cur][e - 1];
    }
}

// ---------------- tf32 mma.sync GEMM (R4 mainloop + peeled tail) -------------------
// All operands pre-rounded tf32 in gmem, row-major K-contiguous. CTA 128x128, BK=32.
// EPI 0: C = tf32(acc)                                  [raw q-gemm]
// EPI 1: C = tf32(gelu(acc))
// EPI 2: no store; atomicAdd red[(r&2047)] += sum_cols sigmoid(aux[r,c]+acc)
// EPI 3: h = gelu(P[l]*RS[r]*acc + S[l]*vin[r]); C = tf32(h); atomicAdd red0[r] += sum h
// EPI 4: C = RS[r]*aux[r,c] + P[l]*acc + S[l]*vin[r]
#define SW 36           // smem row stride (words): conflict-free frag gathers
#define STG_WORDS (128*SW)          // 4608 words = 18432 B per matrix-stage
#define SMEM_GB (6*STG_WORDS*4)     // 3 stages x (A+B) = 110592 B

template<int EPI>
__global__ __launch_bounds__(256, 2)
void gemm_mma(const float* __restrict__ A, long long Astride,
              const float* __restrict__ Bt0, const float* __restrict__ Bt1,
              float* C0, float* C1,
              const float* __restrict__ aux,
              const float* __restrict__ P, const float* __restrict__ S,
              const float* __restrict__ vin,
              const float* __restrict__ RS,
              float* red0, float* red1) {
    extern __shared__ uint32_t smemBuf[];
    const uint32_t sbase = smem_u32(smemBuf);

    const int tid  = threadIdx.x;
    const int lane = tid & 31, warp = tid >> 5;
    const int wm = warp >> 2, wn = warp & 3;       // 2 x 4 warp grid
    const int qr = lane >> 2, qk = lane & 3;
    const int rowBase = blockIdx.y * 128;
    const int colBase = blockIdx.x * 128;
    const int z = blockIdx.z;
    const float* Ab = A + (long long)z * Astride;
    const float* Bt = z ? Bt1 : Bt0;
    float* C        = z ? C1 : C0;

    float acc[4][4][4];
    #pragma unroll
    for (int mf = 0; mf < 4; mf++)
        #pragma unroll
        for (int nf = 0; nf < 4; nf++)
            #pragma unroll
            for (int i = 0; i < 4; i++) acc[mf][nf][i] = 0.0f;

    // per-thread load coords (4 x 16B each for A and B per BK=32 chunk)
    const int lr = tid >> 3;
    const int lc = (tid & 7) * 4;

    auto issue = [&](int kc, int s) {
        const int k0 = kc * 32;
        const uint32_t abase = sbase + s * (STG_WORDS * 4);
        const uint32_t bbase = sbase + (3 + s) * (STG_WORDS * 4);
        #pragma unroll
        for (int i = 0; i < 4; i++) {
            int row = lr + i * 32;
            const float* ga = Ab + (long long)(rowBase + row) * DD + k0 + lc;
            const float* gb = Bt + (long long)(colBase + row) * DD + k0 + lc;
            uint32_t da = abase + (row * SW + lc) * 4;
            uint32_t db = bbase + (row * SW + lc) * 4;
            asm volatile("cp.async.cg.shared.global [%0], [%1], 16;"
                :: "r"(da), "l"(__cvta_generic_to_global(ga)));
            asm volatile("cp.async.cg.shared.global [%0], [%1], 16;"
                :: "r"(db), "l"(__cvta_generic_to_global(gb)));
        }
        asm volatile("cp.async.commit_group;" ::: "memory");
    };

    auto compute = [&](int s) {
        const uint32_t* As = smemBuf + s * STG_WORDS;
        const uint32_t* Bs = smemBuf + (3 + s) * STG_WORDS;
        #pragma unroll
        for (int ks = 0; ks < 4; ks++) {
            uint32_t a[4][4], b[4][2];
            const uint32_t* ap = &As[(wm * 64 + qr) * SW + ks * 8 + qk];
            #pragma unroll
            for (int mf = 0; mf < 4; mf++) {
                a[mf][0] = ap[(mf * 16    ) * SW];
                a[mf][1] = ap[(mf * 16 + 8) * SW];
                a[mf][2] = ap[(mf * 16    ) * SW + 4];
                a[mf][3] = ap[(mf * 16 + 8) * SW + 4];
            }
            const uint32_t* bp = &Bs[(wn * 32 + qr) * SW + ks * 8 + qk];
            #pragma unroll
            for (int nf = 0; nf < 4; nf++) {
                b[nf][0] = bp[nf * 8 * SW];
                b[nf][1] = bp[nf * 8 * SW + 4];
            }
            #pragma unroll
            for (int mf = 0; mf < 4; mf++)
                #pragma unroll
                for (int nf = 0; nf < 4; nf++)
                    asm volatile(
                        "mma.sync.aligned.m16n8k8.row.col.f32.tf32.tf32.f32 "
                        "{%0,%1,%2,%3}, {%4,%5,%6,%7}, {%8,%9}, {%0,%1,%2,%3};"
                        : "+f"(acc[mf][nf][0]), "+f"(acc[mf][nf][1]),
                          "+f"(acc[mf][nf][2]), "+f"(acc[mf][nf][3])
                        : "r"(a[mf][0]), "r"(a[mf][1]), "r"(a[mf][2]), "r"(a[mf][3]),
                          "r"(b[nf][0]), "r"(b[nf][1]));
        }
    };

    issue(0, 0);
    issue(1, 1);

    // Mainloop kc=0..14: constant wait_group 1 (R4 schedule). Last chunk peeled.
    int s = 0;
    for (int kc = 0; kc < 15; kc++) {
        asm volatile("cp.async.wait_group 1;" ::: "memory");
        __syncthreads();
        compute(s);
        if (kc < 14) issue(kc + 2, (s + 2) % 3);
        s = (s + 1) % 3;
    }
    // Peeled tail: only group 15 pending -> must wait_group 0 (race fix).
    asm volatile("cp.async.wait_group 0;" ::: "memory");
    __syncthreads();
    compute(s);

    // ---- epilogue ----
    float* red = (EPI == 2) ? (z ? red1 : red0) : red0;
    const int cBase = colBase + wn * 32 + 2 * qk;

    #pragma unroll
    for (int mf = 0; mf < 4; mf++) {
        #pragma unroll
        for (int half_ = 0; half_ < 2; half_++) {
            int r = rowBase + wm * 64 + mf * 16 + qr + half_ * 8;
            int l = r & (LL - 1);
            int ci = half_ * 2;
            float part = 0.0f;
            float pl = 0.f, sl = 0.f, vv = 0.f, rsv = 0.f;
            if (EPI == 3 || EPI == 4) { pl = P[l]; sl = S[l]; vv = vin[r]; rsv = RS[r]; }
            long long ro = (long long)r * DD;

            #pragma unroll
            for (int nf = 0; nf < 4; nf++) {
                float v0 = acc[mf][nf][ci], v1 = acc[mf][nf][ci + 1];
                long long off = ro + cBase + nf * 8;
                if (EPI == 0) {
                    float2 o = { tf32_round(v0), tf32_round(v1) };
                    *(float2*)(C + off) = o;
                } else if (EPI == 1) {
                    float2 o = { tf32_round(gelu_exact(v0)), tf32_round(gelu_exact(v1)) };
                    *(float2*)(C + off) = o;
                } else if (EPI == 2) {
                    float2 a2 = *(const float2*)(aux + off);
                    part += sigm(a2.x + v0) + sigm(a2.y + v1);
                } else if (EPI == 3) {
                    float h0 = gelu_exact(pl * (rsv * v0) + sl * vv);
                    float h1 = gelu_exact(pl * (rsv * v1) + sl * vv);
                    part += h0 + h1;
                    float2 o = { tf32_round(h0), tf32_round(h1) };
                    *(float2*)(C + off) = o;
                } else if (EPI == 4) {
                    float2 a2 = *(const float2*)(aux + off);
                    float2 o = { rsv * a2.x + pl * v0 + sl * vv,
                                 rsv * a2.y + pl * v1 + sl * vv };
                    *(float2*)(C + off) = o;
                }
            }
            if (EPI == 2 || EPI == 3) {
                part += __shfl_xor_sync(0xffffffffu, part, 1);
                part += __shfl_xor_sync(0xffffffffu, part, 2);
                if (qk == 0) {
                    if (EPI == 2) atomicAdd(&red[l], part);
                    else          atomicAdd(&red[r], part);
                }
            }
        }
    }
}

// ---------------- launcher ----------------
extern "C" void kernel_launch(void* const* d_in, const int* in_sizes, int n_in,
                              void* d_out, int out_size) {
    const float* x        = (const float*)d_in[0];
    const float* conv_w   = (const float*)d_in[1];
    const float* conv_b   = (const float*)d_in[2];
    const float* q_w      = (const float*)d_in[3];
    const float* mem_w1   = (const float*)d_in[4];
    const float* mem_w2   = (const float*)d_in[5];
    const float* eta_w1   = (const float*)d_in[6];
    const float* eta_w2   = (const float*)d_in[7];
    const float* alpha_w1 = (const float*)d_in[8];
    const float* alpha_w2 = (const float*)d_in[9];
    float* out = (float*)d_out;

    float *xct, *h1, *hm, *accum, *ps, *qsum, *rs, *wt;
    cudaGetSymbolAddress((void**)&xct,   g_xct);
    cudaGetSymbolAddress((void**)&h1,    g_h1);
    cudaGetSymbolAddress((void**)&hm,    g_hm);
    cudaGetSymbolAddress((void**)&accum, g_accum);
    cudaGetSymbolAddress((void**)&ps,    g_ps);
    cudaGetSymbolAddress((void**)&qsum,  g_qsum);
    cudaGetSymbolAddress((void**)&rs,    g_rs);
    cudaGetSymbolAddress((void**)&wt,    g_wt);

    float* hs        = accum;
    float* eta_sum   = accum + MT;
    float* alpha_sum = accum + MT + LL;
    float* Pp = ps;
    float* Ss = ps + LL;

    static bool attr_done = false;
    if (!attr_done) {
        cudaFuncSetAttribute(gemm_mma<0>, cudaFuncAttributeMaxDynamicSharedMemorySize, SMEM_GB);
        cudaFuncSetAttribute(gemm_mma<1>, cudaFuncAttributeMaxDynamicSharedMemorySize, SMEM_GB);
        cudaFuncSetAttribute(gemm_mma<2>, cudaFuncAttributeMaxDynamicSharedMemorySize, SMEM_GB);
        cudaFuncSetAttribute(gemm_mma<3>, cudaFuncAttributeMaxDynamicSharedMemorySize, SMEM_GB);
        cudaFuncSetAttribute(gemm_mma<4>, cudaFuncAttributeMaxDynamicSharedMemorySize, SMEM_GB);
        attr_done = true;
    }

    // 0) zero atomic accumulators
    {
        int n = MT + 2 * LL;
        zero_kernel<<<(n + 255) / 256, 256>>>(accum, n);
    }
    // 0b) weights -> transposed + tf32
    prep_weights<<<dim3(16, 16, 7), dim3(32, 8)>>>(eta_w1, alpha_w1, eta_w2, alpha_w2,
                                                   q_w, mem_w1, mem_w2, wt);
    // 1) conv -> xct (tf32 only)
    conv_kernel<<<(MT * (DD/4) + 255) / 256, 256>>>(x, conv_w, conv_b, xct);

    dim3 grid2(DD / 128, MT / 128, 2);
    dim3 grid1(DD / 128, MT / 128, 1);
    float* wt0 = wt + 0LL * DD * DD;  // eta_w1^T
    float* wt1 = wt + 1LL * DD * DD;  // alpha_w1^T
    float* wt2 = wt + 2LL * DD * DD;  // eta_w2^T
    float* wt3 = wt + 3LL * DD * DD;  // alpha_w2^T
    float* wt4 = wt + 4LL * DD * DD;  // q_w
    float* wt5 = wt + 5LL * DD * DD;  // mem_w1^T
    float* wt6 = wt + 6LL * DD * DD;  // mem_w2^T

    // 2) batched xct @ {eta_w1, alpha_w1} -> tf32(gelu) -> h1[z]
    gemm_mma<1><<<grid2, 256, SMEM_GB>>>(xct, 0LL, wt0, wt1, h1, h1 + SZ,
                                         nullptr, nullptr, nullptr, nullptr, nullptr,
                                         nullptr, nullptr);
    // 3) batched h1[z] @ {eta_w2, alpha_w2} -> sigmoid(xct + .) -> per-l sums
    gemm_mma<2><<<grid2, 256, SMEM_GB>>>(h1, SZ, wt2, wt3, nullptr, nullptr,
                                         xct, nullptr, nullptr, nullptr, nullptr,
                                         eta_sum, alpha_sum);
    // 4) xct @ q_w^T -> hm (tf32-rounded raw q-gemm)
    gemm_mma<0><<<grid1, 256, SMEM_GB>>>(xct, 0LL, wt4, wt4, hm, hm,
                                         nullptr, nullptr, nullptr, nullptr, nullptr,
                                         nullptr, nullptr);
    // 5) row norms -> rs, qsum (reduction only)
    rownorm_kernel<<<MT, 128>>>(hm, rs, qsum);
    // 6) parallel affine scan -> p, s
    scan_kernel<<<1, 1024>>>(eta_sum, ps);
    // 7) hm @ mem_w1, epilogue folds l2norm scale: gelu(P*RS*acc + S*qsum) -> h1, hs
    gemm_mma<3><<<grid1, 256, SMEM_GB>>>(hm, 0LL, wt5, wt5, h1, h1,
                                         nullptr, Pp, Ss, qsum, rs,
                                         hs, nullptr);
    // 8) h1 @ mem_w2, final epilogue: out = RS*hm + P*acc + S*hs
    gemm_mma<4><<<grid1, 256, SMEM_GB>>>(h1, 0LL, wt6, wt6, out, out,
                                         hm, Pp, Ss, hs, rs,
                                         nullptr, nullptr);
}

// round 13
// speedup vs baseline: 1.7273x; 1.0911x over previous
#include <cuda_runtime.h>
#include <math.h>
#include <stdint.h>

// Problem sizes (fixed by the reference)
#define BB 8
#define LL 2048
#define DD 512
#define MT (BB*LL)          // 16384 rows
#define SZ ((long long)MT*DD)

// ---------------- scratch (device globals; no allocation allowed) ----------------
__device__ float g_xct[MT*DD];       // conv output, tf32-rounded (GEMM A + EPI2 aux)
__device__ float g_h1[2*MT*DD];      // tf32 gelu(xc@{eta,alpha}w1); later gemm<3> output
__device__ float g_hm[MT*DD];        // raw q-gemm out, tf32-rounded (A of gemm<3>, aux of gemm<4>)
__device__ float g_accum[MT + 2*LL]; // [0:MT) hs rowsums, [MT:MT+LL) eta sum, [MT+LL:) alpha sum
__device__ float g_ps[2*LL];         // [0:LL) p,  [LL:2LL) s
__device__ float g_qsum[MT];         // s_r * rowsum(hm_r)
__device__ float g_rs[MT];           // per-row l2norm scale s_r
__device__ float g_wt[7*DD*DD];      // transposed+tf32-rounded weights

__device__ __forceinline__ float gelu_exact(float x) {
    return 0.5f * x * (1.0f + erff(x * 0.70710678118654752f));
}
__device__ __forceinline__ float sigm(float x) {
    return 1.0f / (1.0f + expf(-x));
}
__device__ __forceinline__ uint32_t tf32_bits(float x) {
    uint32_t u; asm("cvt.rna.tf32.f32 %0, %1;" : "=r"(u) : "f"(x)); return u;
}
__device__ __forceinline__ float tf32_round(float x) {
    return __uint_as_float(tf32_bits(x));
}
__device__ __forceinline__ uint32_t smem_u32(const void* p) {
    uint32_t a;
    asm("{ .reg .u64 t; cvta.to.shared.u64 t, %1; cvt.u32.u64 %0, t; }" : "=r"(a) : "l"(p));
    return a;
}

// ---------------- zero accumulators ----------------
__global__ void zero_kernel(float* a, int n) {
    int i = blockIdx.x * blockDim.x + threadIdx.x;
    if (i < n) a[i] = 0.0f;
}

// ---------------- prep weights: transpose (or copy) + tf32 round ----------------
// slots: 0 eta_w1^T, 1 alpha_w1^T, 2 eta_w2^T, 3 alpha_w2^T, 4 q_w (copy), 5 mem_w1^T, 6 mem_w2^T
__global__ void prep_weights(const float* __restrict__ ew1, const float* __restrict__ aw1,
                             const float* __restrict__ ew2, const float* __restrict__ aw2,
                             const float* __restrict__ qw,  const float* __restrict__ mw1,
                             const float* __restrict__ mw2, float* __restrict__ wt) {
    __shared__ float tile[32][33];
    int zi = blockIdx.z;
    const float* src; bool tr = true;
    switch (zi) {
        case 0: src = ew1; break;
        case 1: src = aw1; break;
        case 2: src = ew2; break;
        case 3: src = aw2; break;
        case 4: src = qw; tr = false; break;
        case 5: src = mw1; break;
        default: src = mw2; break;
    }
    float* dst = wt + (long long)zi * DD * DD;
    int bx = blockIdx.x * 32, by = blockIdx.y * 32;
    int tx = threadIdx.x, ty = threadIdx.y;  // (32, 8)
    if (tr) {
        #pragma unroll
        for (int i = 0; i < 32; i += 8)
            tile[ty + i][tx] = src[(long long)(by + ty + i) * DD + bx + tx];
        __syncthreads();
        #pragma unroll
        for (int i = 0; i < 32; i += 8)
            dst[(long long)(bx + ty + i) * DD + by + tx] = tf32_round(tile[tx][ty + i]);
    } else {
        #pragma unroll
        for (int i = 0; i < 32; i += 8)
            dst[(long long)(by + ty + i) * DD + bx + tx] =
                tf32_round(src[(long long)(by + ty + i) * DD + bx + tx]);
    }
}

// ---------------- causal depthwise conv (k=4, left pad 3) + bias -> tf32 ----------
__global__ void conv_kernel(const float* __restrict__ x, const float* __restrict__ w,
                            const float* __restrict__ bias, float* __restrict__ xct) {
    int idx = blockIdx.x * blockDim.x + threadIdx.x;
    if (idx >= MT * (DD/4)) return;
    int d4 = idx & 127;
    int r  = idx >> 7;
    int l  = r & (LL-1);
    int d  = d4 * 4;
    float4 out = *(const float4*)(bias + d);
    #pragma unroll
    for (int k = 0; k < 4; k++) {
        int li = l + k - 3;
        if (li >= 0) {
            float4 xv = *(const float4*)(x + (long long)(r + k - 3) * DD + d);
            out.x += xv.x * w[(d+0)*4 + k];
            out.y += xv.y * w[(d+1)*4 + k];
            out.z += xv.z * w[(d+2)*4 + k];
            out.w += xv.w * w[(d+3)*4 + k];
        }
    }
    float4 rt = { tf32_round(out.x), tf32_round(out.y), tf32_round(out.z), tf32_round(out.w) };
    *(float4*)(xct + (long long)r * DD + d) = rt;
}

// ---------------- row norms: s_r = 1/max(||hm_r||, eps), qsum_r = s_r*sum(hm_r) ----
__global__ void rownorm_kernel(const float* __restrict__ G, float* __restrict__ rs,
                               float* __restrict__ qsum) {
    int r = blockIdx.x;
    int t = threadIdx.x;   // 128
    float4 v = ((const float4*)(G + (long long)r * DD))[t];
    float ss = v.x*v.x + v.y*v.y + v.z*v.z + v.w*v.w;
    float sg = v.x + v.y + v.z + v.w;
    #pragma unroll
    for (int o = 16; o > 0; o >>= 1) {
        ss += __shfl_down_sync(0xffffffffu, ss, o);
        sg += __shfl_down_sync(0xffffffffu, sg, o);
    }
    __shared__ float sh_ss[4], sh_sg[4];
    int w = t >> 5;
    if ((t & 31) == 0) { sh_ss[w] = ss; sh_sg[w] = sg; }
    __syncthreads();
    if (t == 0) {
        float S  = sh_ss[0] + sh_ss[1] + sh_ss[2] + sh_ss[3];
        float Gs = sh_sg[0] + sh_sg[1] + sh_sg[2] + sh_sg[3];
        float scale = 1.0f / fmaxf(sqrtf(S), 1e-12f);
        rs[r]   = scale;
        qsum[r] = Gs * scale;
    }
}

// ---------------- parallel affine scan for p_t, s_t ----------------
__global__ void scan_kernel(const float* __restrict__ red, float* __restrict__ PS) {
    __shared__ float Aa[2][LL];
    __shared__ float Bb[2][LL];
    const float inv = 1.0f / (float)(BB * DD);
    int t = threadIdx.x;  // 1024
    #pragma unroll
    for (int h = 0; h < 2; h++) {
        int e = t + h * 1024;
        Aa[0][e] = red[LL + e] * inv;        // alpha mean
        Bb[0][e] = -0.01f * red[e] * inv;    // -0.01 * eta mean
    }
    int cur = 0;
    for (int d = 1; d < LL; d <<= 1) {
        __syncthreads();
        #pragma unroll
        for (int h = 0; h < 2; h++) {
            int e = t + h * 1024;
            float A2 = Aa[cur][e], B2 = Bb[cur][e];
            if (e >= d) {
                float A1 = Aa[cur][e - d], B1 = Bb[cur][e - d];
                B2 = A2 * B1 + B2;
                A2 = A1 * A2;
            }
            Aa[cur ^ 1][e] = A2;
            Bb[cur ^ 1][e] = B2;
        }
        cur ^= 1;
    }
    __syncthreads();
    #pragma unroll
    for (int h = 0; h < 2; h++) {
        int e = t + h * 1024;
        PS[e]      = (e == 0) ? 1.0f : Aa[cur][e - 1];
        PS[LL + e] = (e == 0) ? 0.0f : Bb[cur][e - 1];
    }
}

// ---------------- tf32 mma.sync GEMM, ldmatrix-b16 fragment loads ------------------
// All operands pre-rounded tf32 in gmem, row-major K-contiguous. CTA 128x128, BK=32.
// ldmatrix.m8n8.x4.b16 trick: an 8x8 b16 matrix row = 16B = 4 tf32, depositing tf32
// element (row t/4, col t%4) per thread = the m16n8k8 tf32 fragment quadrant.
// Addresses are per-row -> works with the SW=36 padded smem unchanged; math is
// bitwise identical to the scalar-LDS version.
// EPI 0: C = tf32(acc)
// EPI 1: C = tf32(gelu(acc))
// EPI 2: no store; atomicAdd red[(r&2047)] += sum_cols sigmoid(aux[r,c]+acc)
// EPI 3: h = gelu(P[l]*RS[r]*acc + S[l]*vin[r]); C = tf32(h); atomicAdd red0[r] += sum h
// EPI 4: C = RS[r]*aux[r,c] + P[l]*acc + S[l]*vin[r]
// EPI 5: merged: z<2 -> EPI1 into C0/C1; z==2 -> EPI0 into C2 (B from Bt2)
#define SW 36           // smem row stride (words)
#define STG_WORDS (128*SW)          // 4608 words = 18432 B per matrix-stage
#define SMEM_GB (6*STG_WORDS*4)     // 3 stages x (A+B) = 110592 B

template<int EPI>
__global__ __launch_bounds__(256, 2)
void gemm_mma(const float* __restrict__ A, long long Astride,
              const float* __restrict__ Bt0, const float* __restrict__ Bt1,
              const float* __restrict__ Bt2,
              float* C0, float* C1, float* C2,
              const float* __restrict__ aux,
              const float* __restrict__ P, const float* __restrict__ S,
              const float* __restrict__ vin,
              const float* __restrict__ RS,
              float* red0, float* red1) {
    extern __shared__ uint32_t smemBuf[];
    const uint32_t sbase = smem_u32(smemBuf);

    const int tid  = threadIdx.x;
    const int lane = tid & 31, warp = tid >> 5;
    const int wm = warp >> 2, wn = warp & 3;       // 2 x 4 warp grid
    const int qr = lane >> 2, qk = lane & 3;
    const int rowBase = blockIdx.y * 128;
    const int colBase = blockIdx.x * 128;
    const int z = blockIdx.z;
    const float* Ab = A + (long long)z * Astride;
    const float* Bt = (EPI == 5) ? (z == 0 ? Bt0 : (z == 1 ? Bt1 : Bt2))
                                 : (z ? Bt1 : Bt0);
    float* C        = z ? C1 : C0;

    float acc[4][4][4];
    #pragma unroll
    for (int mf = 0; mf < 4; mf++)
        #pragma unroll
        for (int nf = 0; nf < 4; nf++)
            #pragma unroll
            for (int i = 0; i < 4; i++) acc[mf][nf][i] = 0.0f;

    // per-thread load coords (4 x 16B each for A and B per BK=32 chunk)
    const int lr = tid >> 3;
    const int lc = (tid & 7) * 4;

    auto issue = [&](int kc, int s) {
        const int k0 = kc * 32;
        const uint32_t abase = sbase + s * (STG_WORDS * 4);
        const uint32_t bbase = sbase + (3 + s) * (STG_WORDS * 4);
        #pragma unroll
        for (int i = 0; i < 4; i++) {
            int row = lr + i * 32;
            const float* ga = Ab + (long long)(rowBase + row) * DD + k0 + lc;
            const float* gb = Bt + (long long)(colBase + row) * DD + k0 + lc;
            uint32_t da = abase + (row * SW + lc) * 4;
            uint32_t db = bbase + (row * SW + lc) * 4;
            asm volatile("cp.async.cg.shared.global [%0], [%1], 16;"
                :: "r"(da), "l"(__cvta_generic_to_global(ga)));
            asm volatile("cp.async.cg.shared.global [%0], [%1], 16;"
                :: "r"(db), "l"(__cvta_generic_to_global(gb)));
        }
        asm volatile("cp.async.commit_group;" ::: "memory");
    };

    // ldmatrix per-lane row-address offsets (bytes)
    // A: lanes 0-7: rows 0-7 khalf0 | 8-15: rows 8-15 khalf0 | 16-23: rows 0-7 khalf1 | 24-31: rows 8-15 khalf1
    const uint32_t aoff = (uint32_t)(((lane & 15) * SW + (lane >> 4) * 4) * 4);
    // B: lanes 0-7: rows 0-7 khalf0 | 8-15: rows 0-7 khalf1 | 16-23: rows 8-15 khalf0 | 24-31: rows 8-15 khalf1
    const uint32_t boff = (uint32_t)((((lane & 7) + ((lane >> 4) << 3)) * SW
                                      + ((lane >> 3) & 1) * 4) * 4);
    const uint32_t aWarp = (uint32_t)(wm * 64) * SW * 4;
    const uint32_t bWarp = (uint32_t)(wn * 32) * SW * 4;

    auto compute = [&](int s) {
        const uint32_t aStg = sbase + s * (STG_WORDS * 4) + aWarp + aoff;
        const uint32_t bStg = sbase + (3 + s) * (STG_WORDS * 4) + bWarp + boff;
        #pragma unroll
        for (int ks = 0; ks < 4; ks++) {
            uint32_t a[4][4], b[4][2];
            #pragma unroll
            for (int mf = 0; mf < 4; mf++) {
                uint32_t addr = aStg + (uint32_t)((mf * 16 * SW + ks * 8) * 4);
                asm volatile("ldmatrix.sync.aligned.m8n8.x4.shared.b16 {%0,%1,%2,%3}, [%4];"
                    : "=r"(a[mf][0]), "=r"(a[mf][1]), "=r"(a[mf][2]), "=r"(a[mf][3])
                    : "r"(addr));
            }
            #pragma unroll
            for (int nfp = 0; nfp < 2; nfp++) {
                uint32_t addr = bStg + (uint32_t)((nfp * 16 * SW + ks * 8) * 4);
                asm volatile("ldmatrix.sync.aligned.m8n8.x4.shared.b16 {%0,%1,%2,%3}, [%4];"
                    : "=r"(b[2*nfp][0]), "=r"(b[2*nfp][1]),
                      "=r"(b[2*nfp+1][0]), "=r"(b[2*nfp+1][1])
                    : "r"(addr));
            }
            #pragma unroll
            for (int mf = 0; mf < 4; mf++)
                #pragma unroll
                for (int nf = 0; nf < 4; nf++)
                    asm volatile(
                        "mma.sync.aligned.m16n8k8.row.col.f32.tf32.tf32.f32 "
                        "{%0,%1,%2,%3}, {%4,%5,%6,%7}, {%8,%9}, {%0,%1,%2,%3};"
                        : "+f"(acc[mf][nf][0]), "+f"(acc[mf][nf][1]),
                          "+f"(acc[mf][nf][2]), "+f"(acc[mf][nf][3])
                        : "r"(a[mf][0]), "r"(a[mf][1]), "r"(a[mf][2]), "r"(a[mf][3]),
                          "r"(b[nf][0]), "r"(b[nf][1]));
        }
    };

    issue(0, 0);
    issue(1, 1);

    // Mainloop kc=0..14: constant wait_group 1 (proven schedule). Last chunk peeled.
    int s = 0;
    for (int kc = 0; kc < 15; kc++) {
        asm volatile("cp.async.wait_group 1;" ::: "memory");
        __syncthreads();
        compute(s);
        if (kc < 14) issue(kc + 2, (s + 2) % 3);
        s = (s + 1) % 3;
    }
    // Peeled tail: only group 15 pending -> wait_group 0 (race fix).
    asm volatile("cp.async.wait_group 0;" ::: "memory");
    __syncthreads();
    compute(s);

    // ---- epilogue ----
    float* red = (EPI == 2) ? (z ? red1 : red0) : red0;
    const int cBase = colBase + wn * 32 + 2 * qk;
    const bool plainZ = (EPI == 5) && (z == 2);
    float* Cm = plainZ ? C2 : C;

    #pragma unroll
    for (int mf = 0; mf < 4; mf++) {
        #pragma unroll
        for (int half_ = 0; half_ < 2; half_++) {
            int r = rowBase + wm * 64 + mf * 16 + qr + half_ * 8;
            int l = r & (LL - 1);
            int ci = half_ * 2;
            float part = 0.0f;
            float pl = 0.f, sl = 0.f, vv = 0.f, rsv = 0.f;
            if (EPI == 3 || EPI == 4) { pl = P[l]; sl = S[l]; vv = vin[r]; rsv = RS[r]; }
            long long ro = (long long)r * DD;

            #pragma unroll
            for (int nf = 0; nf < 4; nf++) {
                float v0 = acc[mf][nf][ci], v1 = acc[mf][nf][ci + 1];
                long long off = ro + cBase + nf * 8;
                if (EPI == 0) {
                    float2 o = { tf32_round(v0), tf32_round(v1) };
                    *(float2*)(C + off) = o;
                } else if (EPI == 1) {
                    float2 o = { tf32_round(gelu_exact(v0)), tf32_round(gelu_exact(v1)) };
                    *(float2*)(C + off) = o;
                } else if (EPI == 2) {
                    float2 a2 = *(const float2*)(aux + off);
                    part += sigm(a2.x + v0) + sigm(a2.y + v1);
                } else if (EPI == 3) {
                    float h0 = gelu_exact(pl * (rsv * v0) + sl * vv);
                    float h1 = gelu_exact(pl * (rsv * v1) + sl * vv);
                    part += h0 + h1;
                    float2 o = { tf32_round(h0), tf32_round(h1) };
                    *(float2*)(C + off) = o;
                } else if (EPI == 4) {
                    float2 a2 = *(const float2*)(aux + off);
                    float2 o = { rsv * a2.x + pl * v0 + sl * vv,
                                 rsv * a2.y + pl * v1 + sl * vv };
                    *(float2*)(C + off) = o;
                } else if (EPI == 5) {
                    float2 o;
                    if (plainZ) { o.x = tf32_round(v0); o.y = tf32_round(v1); }
                    else        { o.x = tf32_round(gelu_exact(v0));
                                  o.y = tf32_round(gelu_exact(v1)); }
                    *(float2*)(Cm + off) = o;
                }
            }
            if (EPI == 2 || EPI == 3) {
                part += __shfl_xor_sync(0xffffffffu, part, 1);
                part += __shfl_xor_sync(0xffffffffu, part, 2);
                if (qk == 0) {
                    if (EPI == 2) atomicAdd(&red[l], part);
                    else          atomicAdd(&red[r], part);
                }
            }
        }
    }
}

// ---------------- launcher ----------------
extern "C" void kernel_launch(void* const* d_in, const int* in_sizes, int n_in,
                              void* d_out, int out_size) {
    const float* x        = (const float*)d_in[0];
    const float* conv_w   = (const float*)d_in[1];
    const float* conv_b   = (const float*)d_in[2];
    const float* q_w      = (const float*)d_in[3];
    const float* mem_w1   = (const float*)d_in[4];
    const float* mem_w2   = (const float*)d_in[5];
    const float* eta_w1   = (const float*)d_in[6];
    const float* eta_w2   = (const float*)d_in[7];
    const float* alpha_w1 = (const float*)d_in[8];
    const float* alpha_w2 = (const float*)d_in[9];
    float* out = (float*)d_out;

    float *xct, *h1, *hm, *accum, *ps, *qsum, *rs, *wt;
    cudaGetSymbolAddress((void**)&xct,   g_xct);
    cudaGetSymbolAddress((void**)&h1,    g_h1);
    cudaGetSymbolAddress((void**)&hm,    g_hm);
    cudaGetSymbolAddress((void**)&accum, g_accum);
    cudaGetSymbolAddress((void**)&ps,    g_ps);
    cudaGetSymbolAddress((void**)&qsum,  g_qsum);
    cudaGetSymbolAddress((void**)&rs,    g_rs);
    cudaGetSymbolAddress((void**)&wt,    g_wt);

    float* hs        = accum;
    float* eta_sum   = accum + MT;
    float* alpha_sum = accum + MT + LL;
    float* Pp = ps;
    float* Ss = ps + LL;

    static bool attr_done = false;
    if (!attr_done) {
        cudaFuncSetAttribute(gemm_mma<2>, cudaFuncAttributeMaxDynamicSharedMemorySize, SMEM_GB);
        cudaFuncSetAttribute(gemm_mma<3>, cudaFuncAttributeMaxDynamicSharedMemorySize, SMEM_GB);
        cudaFuncSetAttribute(gemm_mma<4>, cudaFuncAttributeMaxDynamicSharedMemorySize, SMEM_GB);
        cudaFuncSetAttribute(gemm_mma<5>, cudaFuncAttributeMaxDynamicSharedMemorySize, SMEM_GB);
        attr_done = true;
    }

    // 0) zero atomic accumulators
    {
        int n = MT + 2 * LL;
        zero_kernel<<<(n + 255) / 256, 256>>>(accum, n);
    }
    // 0b) weights -> transposed + tf32
    prep_weights<<<dim3(16, 16, 7), dim3(32, 8)>>>(eta_w1, alpha_w1, eta_w2, alpha_w2,
                                                   q_w, mem_w1, mem_w2, wt);
    // 1) conv -> xct (tf32 only)
    conv_kernel<<<(MT * (DD/4) + 255) / 256, 256>>>(x, conv_w, conv_b, xct);

    dim3 grid3(DD / 128, MT / 128, 3);
    dim3 grid2(DD / 128, MT / 128, 2);
    dim3 grid1(DD / 128, MT / 128, 1);
    float* wt0 = wt + 0LL * DD * DD;  // eta_w1^T
    float* wt1 = wt + 1LL * DD * DD;  // alpha_w1^T
    float* wt2 = wt + 2LL * DD * DD;  // eta_w2^T
    float* wt3 = wt + 3LL * DD * DD;  // alpha_w2^T
    float* wt4 = wt + 4LL * DD * DD;  // q_w
    float* wt5 = wt + 5LL * DD * DD;  // mem_w1^T
    float* wt6 = wt + 6LL * DD * DD;  // mem_w2^T

    // 2) merged: z<2: xct @ {eta_w1, alpha_w1} -> tf32(gelu) -> h1[z]
    //            z==2: xct @ q_w^T -> tf32(acc) -> hm
    gemm_mma<5><<<grid3, 256, SMEM_GB>>>(xct, 0LL, wt0, wt1, wt4, h1, h1 + SZ, hm,
                                         nullptr, nullptr, nullptr, nullptr, nullptr,
                                         nullptr, nullptr);
    // 3) batched h1[z] @ {eta_w2, alpha_w2} -> sigmoid(xct + .) -> per-l sums
    gemm_mma<2><<<grid2, 256, SMEM_GB>>>(h1, SZ, wt2, wt3, nullptr,
                                         nullptr, nullptr, nullptr,
                                         xct, nullptr, nullptr, nullptr, nullptr,
                                         eta_sum, alpha_sum);
    // 4) row norms -> rs, qsum (reduction only)
    rownorm_kernel<<<MT, 128>>>(hm, rs, qsum);
    // 5) parallel affine scan -> p, s
    scan_kernel<<<1, 1024>>>(eta_sum, ps);
    // 6) hm @ mem_w1, epilogue folds l2norm scale: gelu(P*RS*acc + S*qsum) -> h1, hs
    gemm_mma<3><<<grid1, 256, SMEM_GB>>>(hm, 0LL, wt5, wt5, nullptr, h1, h1, nullptr,
                                         nullptr, Pp, Ss, qsum, rs,
                                         hs, nullptr);
    // 7) h1 @ mem_w2, final epilogue: out = RS*hm + P*acc + S*hs
    gemm_mma<4><<<grid1, 256, SMEM_GB>>>(h1, 0LL, wt6, wt6, nullptr, out, out, nullptr,
                                         hm, Pp, Ss, hs, rs,
                                         nullptr, nullptr);
}

// round 14
// speedup vs baseline: 1.7372x; 1.0057x over previous
#include <cuda_runtime.h>
#include <math.h>
#include <stdint.h>

// Problem sizes (fixed by the reference)
#define BB 8
#define LL 2048
#define DD 512
#define MT (BB*LL)          // 16384 rows
#define SZ ((long long)MT*DD)

// ---------------- scratch (device globals; no allocation allowed) ----------------
__device__ float g_xct[MT*DD];       // conv output, tf32-rounded (GEMM A + EPI2 aux)
__device__ float g_h1[2*MT*DD];      // tf32 gelu(xc@{eta,alpha}w1); later gemm<3> output
__device__ float g_hm[MT*DD];        // raw q-gemm out, tf32-rounded
// accum layout: [0,MT) hs | [MT,MT+LL) eta | [MT+LL,MT+2LL) alpha |
//               [MT+2LL, 2MT+2LL) ss | [2MT+2LL, 3MT+2LL) sg
#define ACC_N (3*MT + 2*LL)
__device__ float g_accum[ACC_N];
__device__ float g_ps[2*LL];         // [0:LL) p,  [LL:2LL) s
__device__ float g_qsum[MT];         // s_r * rowsum(hm_r)
__device__ float g_rs[MT];           // per-row l2norm scale s_r
__device__ float g_wt[7*DD*DD];      // transposed+tf32-rounded weights

__device__ __forceinline__ float gelu_exact(float x) {
    return 0.5f * x * (1.0f + erff(x * 0.70710678118654752f));
}
__device__ __forceinline__ float sigm(float x) {
    return 1.0f / (1.0f + expf(-x));
}
__device__ __forceinline__ uint32_t tf32_bits(float x) {
    uint32_t u; asm("cvt.rna.tf32.f32 %0, %1;" : "=r"(u) : "f"(x)); return u;
}
__device__ __forceinline__ float tf32_round(float x) {
    return __uint_as_float(tf32_bits(x));
}
__device__ __forceinline__ uint32_t smem_u32(const void* p) {
    uint32_t a;
    asm("{ .reg .u64 t; cvta.to.shared.u64 t, %1; cvt.u32.u64 %0, t; }" : "=r"(a) : "l"(p));
    return a;
}

// ---------------- prep weights (+ z==7: zero accum) ----------------
// slots: 0 eta_w1^T, 1 alpha_w1^T, 2 eta_w2^T, 3 alpha_w2^T, 4 q_w (copy), 5 mem_w1^T, 6 mem_w2^T
__global__ void prep_weights(const float* __restrict__ ew1, const float* __restrict__ aw1,
                             const float* __restrict__ ew2, const float* __restrict__ aw2,
                             const float* __restrict__ qw,  const float* __restrict__ mw1,
                             const float* __restrict__ mw2, float* __restrict__ wt,
                             float* __restrict__ accum) {
    __shared__ float tile[32][33];
    int zi = blockIdx.z;
    int tx = threadIdx.x, ty = threadIdx.y;  // (32, 8)
    if (zi == 7) {
        // zero the accum block: 256 blocks x 208 floats
        int blk = blockIdx.y * 16 + blockIdx.x;
        int t = ty * 32 + tx;
        int idx = blk * 208 + t;
        if (t < 208 && idx < ACC_N) accum[idx] = 0.0f;
        return;
    }
    const float* src; bool tr = true;
    switch (zi) {
        case 0: src = ew1; break;
        case 1: src = aw1; break;
        case 2: src = ew2; break;
        case 3: src = aw2; break;
        case 4: src = qw; tr = false; break;
        case 5: src = mw1; break;
        default: src = mw2; break;
    }
    float* dst = wt + (long long)zi * DD * DD;
    int bx = blockIdx.x * 32, by = blockIdx.y * 32;
    if (tr) {
        #pragma unroll
        for (int i = 0; i < 32; i += 8)
            tile[ty + i][tx] = src[(long long)(by + ty + i) * DD + bx + tx];
        __syncthreads();
        #pragma unroll
        for (int i = 0; i < 32; i += 8)
            dst[(long long)(bx + ty + i) * DD + by + tx] = tf32_round(tile[tx][ty + i]);
    } else {
        #pragma unroll
        for (int i = 0; i < 32; i += 8)
            dst[(long long)(by + ty + i) * DD + bx + tx] =
                tf32_round(src[(long long)(by + ty + i) * DD + bx + tx]);
    }
}

// ---------------- causal depthwise conv (k=4, left pad 3) + bias -> tf32 ----------
__global__ void conv_kernel(const float* __restrict__ x, const float* __restrict__ w,
                            const float* __restrict__ bias, float* __restrict__ xct) {
    int idx = blockIdx.x * blockDim.x + threadIdx.x;
    if (idx >= MT * (DD/4)) return;
    int d4 = idx & 127;
    int r  = idx >> 7;
    int l  = r & (LL-1);
    int d  = d4 * 4;
    float4 out = *(const float4*)(bias + d);
    #pragma unroll
    for (int k = 0; k < 4; k++) {
        int li = l + k - 3;
        if (li >= 0) {
            float4 xv = *(const float4*)(x + (long long)(r + k - 3) * DD + d);
            out.x += xv.x * w[(d+0)*4 + k];
            out.y += xv.y * w[(d+1)*4 + k];
            out.z += xv.z * w[(d+2)*4 + k];
            out.w += xv.w * w[(d+3)*4 + k];
        }
    }
    float4 rt = { tf32_round(out.x), tf32_round(out.y), tf32_round(out.z), tf32_round(out.w) };
    *(float4*)(xct + (long long)r * DD + d) = rt;
}

// ---------------- scan (block 0) + row-norm finalize (blocks 1..16) ----------------
__global__ void scan_kernel(const float* __restrict__ red, float* __restrict__ PS,
                            const float* __restrict__ ss, const float* __restrict__ sg,
                            float* __restrict__ rs, float* __restrict__ qsum) {
    if (blockIdx.x > 0) {
        int r = (blockIdx.x - 1) * 1024 + threadIdx.x;
        float scale = 1.0f / fmaxf(sqrtf(ss[r]), 1e-12f);
        rs[r]   = scale;
        qsum[r] = sg[r] * scale;
        return;
    }
    __shared__ float Aa[2][LL];
    __shared__ float Bb[2][LL];
    const float inv = 1.0f / (float)(BB * DD);
    int t = threadIdx.x;  // 1024
    #pragma unroll
    for (int h = 0; h < 2; h++) {
        int e = t + h * 1024;
        Aa[0][e] = red[LL + e] * inv;        // alpha mean
        Bb[0][e] = -0.01f * red[e] * inv;    // -0.01 * eta mean
    }
    int cur = 0;
    for (int d = 1; d < LL; d <<= 1) {
        __syncthreads();
        #pragma unroll
        for (int h = 0; h < 2; h++) {
            int e = t + h * 1024;
            float A2 = Aa[cur][e], B2 = Bb[cur][e];
            if (e >= d) {
                float A1 = Aa[cur][e - d], B1 = Bb[cur][e - d];
                B2 = A2 * B1 + B2;
                A2 = A1 * A2;
            }
            Aa[cur ^ 1][e] = A2;
            Bb[cur ^ 1][e] = B2;
        }
        cur ^= 1;
    }
    __syncthreads();
    #pragma unroll
    for (int h = 0; h < 2; h++) {
        int e = t + h * 1024;
        PS[e]      = (e == 0) ? 1.0f : Aa[cur][e - 1];
        PS[LL + e] = (e == 0) ? 0.0f : Bb[cur][e - 1];
    }
}

// ---------------- tf32 mma.sync GEMM, ldmatrix-b16 fragment loads ------------------
// EPI 2: no store; atomicAdd red[(r&2047)] += sum_cols sigmoid(aux[r,c]+acc)
// EPI 3: h = gelu(P[l]*RS[r]*acc + S[l]*vin[r]); C = tf32(h); atomicAdd red0[r] += sum h
// EPI 4: C = RS[r]*aux[r,c] + P[l]*acc + S[l]*vin[r]
// EPI 5: z<2 -> C = tf32(gelu(acc)); z==2 -> C2 = tf32(acc) + row atomics:
//        red0[r] += sum tf32(v)^2, red1[r] += sum tf32(v)   (fused rownorm)
#define SW 36           // smem row stride (words)
#define STG_WORDS (128*SW)          // 4608 words = 18432 B per matrix-stage
#define SMEM_GB (6*STG_WORDS*4)     // 3 stages x (A+B) = 110592 B

template<int EPI>
__global__ __launch_bounds__(256, 2)
void gemm_mma(const float* __restrict__ A, long long Astride,
              const float* __restrict__ Bt0, const float* __restrict__ Bt1,
              const float* __restrict__ Bt2,
              float* C0, float* C1, float* C2,
              const float* __restrict__ aux,
              const float* __restrict__ P, const float* __restrict__ S,
              const float* __restrict__ vin,
              const float* __restrict__ RS,
              float* red0, float* red1) {
    extern __shared__ uint32_t smemBuf[];
    const uint32_t sbase = smem_u32(smemBuf);

    const int tid  = threadIdx.x;
    const int lane = tid & 31, warp = tid >> 5;
    const int wm = warp >> 2, wn = warp & 3;       // 2 x 4 warp grid
    const int qr = lane >> 2, qk = lane & 3;
    const int rowBase = blockIdx.y * 128;
    const int colBase = blockIdx.x * 128;
    const int z = blockIdx.z;
    const float* Ab = A + (long long)z * Astride;
    const float* Bt = (EPI == 5) ? (z == 0 ? Bt0 : (z == 1 ? Bt1 : Bt2))
                                 : (z ? Bt1 : Bt0);
    float* C        = z ? C1 : C0;

    float acc[4][4][4];
    #pragma unroll
    for (int mf = 0; mf < 4; mf++)
        #pragma unroll
        for (int nf = 0; nf < 4; nf++)
            #pragma unroll
            for (int i = 0; i < 4; i++) acc[mf][nf][i] = 0.0f;

    // per-thread load coords (4 x 16B each for A and B per BK=32 chunk)
    const int lr = tid >> 3;
    const int lc = (tid & 7) * 4;

    auto issue = [&](int kc, int s) {
        const int k0 = kc * 32;
        const uint32_t abase = sbase + s * (STG_WORDS * 4);
        const uint32_t bbase = sbase + (3 + s) * (STG_WORDS * 4);
        #pragma unroll
        for (int i = 0; i < 4; i++) {
            int row = lr + i * 32;
            const float* ga = Ab + (long long)(rowBase + row) * DD + k0 + lc;
            const float* gb = Bt + (long long)(colBase + row) * DD + k0 + lc;
            uint32_t da = abase + (row * SW + lc) * 4;
            uint32_t db = bbase + (row * SW + lc) * 4;
            asm volatile("cp.async.cg.shared.global [%0], [%1], 16;"
                :: "r"(da), "l"(__cvta_generic_to_global(ga)));
            asm volatile("cp.async.cg.shared.global [%0], [%1], 16;"
                :: "r"(db), "l"(__cvta_generic_to_global(gb)));
        }
        asm volatile("cp.async.commit_group;" ::: "memory");
    };

    // ldmatrix per-lane row-address offsets (bytes)
    const uint32_t aoff = (uint32_t)(((lane & 15) * SW + (lane >> 4) * 4) * 4);
    const uint32_t boff = (uint32_t)((((lane & 7) + ((lane >> 4) << 3)) * SW
                                      + ((lane >> 3) & 1) * 4) * 4);
    const uint32_t aWarp = (uint32_t)(wm * 64) * SW * 4;
    const uint32_t bWarp = (uint32_t)(wn * 32) * SW * 4;

    auto compute = [&](int s) {
        const uint32_t aStg = sbase + s * (STG_WORDS * 4) + aWarp + aoff;
        const uint32_t bStg = sbase + (3 + s) * (STG_WORDS * 4) + bWarp + boff;
        #pragma unroll
        for (int ks = 0; ks < 4; ks++) {
            uint32_t a[4][4], b[4][2];
            #pragma unroll
            for (int mf = 0; mf < 4; mf++) {
                uint32_t addr = aStg + (uint32_t)((mf * 16 * SW + ks * 8) * 4);
                asm volatile("ldmatrix.sync.aligned.m8n8.x4.shared.b16 {%0,%1,%2,%3}, [%4];"
                    : "=r"(a[mf][0]), "=r"(a[mf][1]), "=r"(a[mf][2]), "=r"(a[mf][3])
                    : "r"(addr));
            }
            #pragma unroll
            for (int nfp = 0; nfp < 2; nfp++) {
                uint32_t addr = bStg + (uint32_t)((nfp * 16 * SW + ks * 8) * 4);
                asm volatile("ldmatrix.sync.aligned.m8n8.x4.shared.b16 {%0,%1,%2,%3}, [%4];"
                    : "=r"(b[2*nfp][0]), "=r"(b[2*nfp][1]),
                      "=r"(b[2*nfp+1][0]), "=r"(b[2*nfp+1][1])
                    : "r"(addr));
            }
            #pragma unroll
            for (int mf = 0; mf < 4; mf++)
                #pragma unroll
                for (int nf = 0; nf < 4; nf++)
                    asm volatile(
                        "mma.sync.aligned.m16n8k8.row.col.f32.tf32.tf32.f32 "
                        "{%0,%1,%2,%3}, {%4,%5,%6,%7}, {%8,%9}, {%0,%1,%2,%3};"
                        : "+f"(acc[mf][nf][0]), "+f"(acc[mf][nf][1]),
                          "+f"(acc[mf][nf][2]), "+f"(acc[mf][nf][3])
                        : "r"(a[mf][0]), "r"(a[mf][1]), "r"(a[mf][2]), "r"(a[mf][3]),
                          "r"(b[nf][0]), "r"(b[nf][1]));
        }
    };

    issue(0, 0);
    issue(1, 1);

    // Mainloop kc=0..14: constant wait_group 1 (proven schedule). Last chunk peeled.
    int s = 0;
    for (int kc = 0; kc < 15; kc++) {
        asm volatile("cp.async.wait_group 1;" ::: "memory");
        __syncthreads();
        compute(s);
        if (kc < 14) issue(kc + 2, (s + 2) % 3);
        s = (s + 1) % 3;
    }
    // Peeled tail: only group 15 pending -> wait_group 0 (race fix).
    asm volatile("cp.async.wait_group 0;" ::: "memory");
    __syncthreads();
    compute(s);

    // ---- epilogue ----
    float* red = (EPI == 2) ? (z ? red1 : red0) : red0;
    const int cBase = colBase + wn * 32 + 2 * qk;
    const bool plainZ = (EPI == 5) && (z == 2);
    float* Cm = plainZ ? C2 : C;

    #pragma unroll
    for (int mf = 0; mf < 4; mf++) {
        #pragma unroll
        for (int half_ = 0; half_ < 2; half_++) {
            int r = rowBase + wm * 64 + mf * 16 + qr + half_ * 8;
            int l = r & (LL - 1);
            int ci = half_ * 2;
            float part = 0.0f, part2 = 0.0f;
            float pl = 0.f, sl = 0.f, vv = 0.f, rsv = 0.f;
            if (EPI == 3 || EPI == 4) { pl = P[l]; sl = S[l]; vv = vin[r]; rsv = RS[r]; }
            long long ro = (long long)r * DD;

            #pragma unroll
            for (int nf = 0; nf < 4; nf++) {
                float v0 = acc[mf][nf][ci], v1 = acc[mf][nf][ci + 1];
                long long off = ro + cBase + nf * 8;
                if (EPI == 2) {
                    float2 a2 = *(const float2*)(aux + off);
                    part += sigm(a2.x + v0) + sigm(a2.y + v1);
                } else if (EPI == 3) {
                    float h0 = gelu_exact(pl * (rsv * v0) + sl * vv);
                    float h1 = gelu_exact(pl * (rsv * v1) + sl * vv);
                    part += h0 + h1;
                    float2 o = { tf32_round(h0), tf32_round(h1) };
                    *(float2*)(C + off) = o;
                } else if (EPI == 4) {
                    float2 a2 = *(const float2*)(aux + off);
                    float2 o = { rsv * a2.x + pl * v0 + sl * vv,
                                 rsv * a2.y + pl * v1 + sl * vv };
                    *(float2*)(C + off) = o;
                } else if (EPI == 5) {
                    float2 o;
                    if (plainZ) {
                        o.x = tf32_round(v0); o.y = tf32_round(v1);
                        part  += o.x * o.x + o.y * o.y;   // fused rownorm: sumsq
                        part2 += o.x + o.y;               // fused rownorm: sum
                    } else {
                        o.x = tf32_round(gelu_exact(v0));
                        o.y = tf32_round(gelu_exact(v1));
                    }
                    *(float2*)(Cm + off) = o;
                }
            }
            if (EPI == 2 || EPI == 3 || plainZ) {
                part += __shfl_xor_sync(0xffffffffu, part, 1);
                part += __shfl_xor_sync(0xffffffffu, part, 2);
                if (plainZ) {
                    part2 += __shfl_xor_sync(0xffffffffu, part2, 1);
                    part2 += __shfl_xor_sync(0xffffffffu, part2, 2);
                }
                if (qk == 0) {
                    if (EPI == 2)      atomicAdd(&red[l], part);
                    else if (EPI == 3) atomicAdd(&red[r], part);
                    else { atomicAdd(&red0[r], part); atomicAdd(&red1[r], part2); }
                }
            }
        }
    }
}

// ---------------- launcher ----------------
extern "C" void kernel_launch(void* const* d_in, const int* in_sizes, int n_in,
                              void* d_out, int out_size) {
    const float* x        = (const float*)d_in[0];
    const float* conv_w   = (const float*)d_in[1];
    const float* conv_b   = (const float*)d_in[2];
    const float* q_w      = (const float*)d_in[3];
    const float* mem_w1   = (const float*)d_in[4];
    const float* mem_w2   = (const float*)d_in[5];
    const float* eta_w1   = (const float*)d_in[6];
    const float* eta_w2   = (const float*)d_in[7];
    const float* alpha_w1 = (const float*)d_in[8];
    const float* alpha_w2 = (const float*)d_in[9];
    float* out = (float*)d_out;

    float *xct, *h1, *hm, *accum, *ps, *qsum, *rs, *wt;
    cudaGetSymbolAddress((void**)&xct,   g_xct);
    cudaGetSymbolAddress((void**)&h1,    g_h1);
    cudaGetSymbolAddress((void**)&hm,    g_hm);
    cudaGetSymbolAddress((void**)&accum, g_accum);
    cudaGetSymbolAddress((void**)&ps,    g_ps);
    cudaGetSymbolAddress((void**)&qsum,  g_qsum);
    cudaGetSymbolAddress((void**)&rs,    g_rs);
    cudaGetSymbolAddress((void**)&wt,    g_wt);

    float* hs        = accum;                 // [MT]
    float* eta_sum   = accum + MT;            // [LL]
    float* alpha_sum = accum + MT + LL;       // [LL]
    float* ssA       = accum + MT + 2*LL;     // [MT]  row sumsq
    float* sgA       = accum + 2*MT + 2*LL;   // [MT]  row sum
    float* Pp = ps;
    float* Ss = ps + LL;

    static bool attr_done = false;
    if (!attr_done) {
        cudaFuncSetAttribute(gemm_mma<2>, cudaFuncAttributeMaxDynamicSharedMemorySize, SMEM_GB);
        cudaFuncSetAttribute(gemm_mma<3>, cudaFuncAttributeMaxDynamicSharedMemorySize, SMEM_GB);
        cudaFuncSetAttribute(gemm_mma<4>, cudaFuncAttributeMaxDynamicSharedMemorySize, SMEM_GB);
        cudaFuncSetAttribute(gemm_mma<5>, cudaFuncAttributeMaxDynamicSharedMemorySize, SMEM_GB);
        attr_done = true;
    }

    // 0) prep weights + zero accum (z==7)
    prep_weights<<<dim3(16, 16, 8), dim3(32, 8)>>>(eta_w1, alpha_w1, eta_w2, alpha_w2,
                                                   q_w, mem_w1, mem_w2, wt, accum);
    // 1) conv -> xct (tf32 only)
    conv_kernel<<<(MT * (DD/4) + 255) / 256, 256>>>(x, conv_w, conv_b, xct);

    dim3 grid3(DD / 128, MT / 128, 3);
    dim3 grid2(DD / 128, MT / 128, 2);
    dim3 grid1(DD / 128, MT / 128, 1);
    float* wt0 = wt + 0LL * DD * DD;  // eta_w1^T
    float* wt1 = wt + 1LL * DD * DD;  // alpha_w1^T
    float* wt2 = wt + 2LL * DD * DD;  // eta_w2^T
    float* wt3 = wt + 3LL * DD * DD;  // alpha_w2^T
    float* wt4 = wt + 4LL * DD * DD;  // q_w
    float* wt5 = wt + 5LL * DD * DD;  // mem_w1^T
    float* wt6 = wt + 6LL * DD * DD;  // mem_w2^T

    // 2) merged: z<2: xct @ {eta_w1, alpha_w1} -> tf32(gelu) -> h1[z]
    //            z==2: xct @ q_w^T -> tf32(acc) -> hm + fused rownorm atomics
    gemm_mma<5><<<grid3, 256, SMEM_GB>>>(xct, 0LL, wt0, wt1, wt4, h1, h1 + SZ, hm,
                                         nullptr, nullptr, nullptr, nullptr, nullptr,
                                         ssA, sgA);
    // 3) batched h1[z] @ {eta_w2, alpha_w2} -> sigmoid(xct + .) -> per-l sums
    gemm_mma<2><<<grid2, 256, SMEM_GB>>>(h1, SZ, wt2, wt3, nullptr,
                                         nullptr, nullptr, nullptr,
                                         xct, nullptr, nullptr, nullptr, nullptr,
                                         eta_sum, alpha_sum);
    // 4) scan (block 0) + rownorm finalize (blocks 1..16)
    scan_kernel<<<17, 1024>>>(eta_sum, ps, ssA, sgA, rs, qsum);
    // 5) hm @ mem_w1, epilogue folds l2norm scale: gelu(P*RS*acc + S*qsum) -> h1, hs
    gemm_mma<3><<<grid1, 256, SMEM_GB>>>(hm, 0LL, wt5, wt5, nullptr, h1, h1, nullptr,
                                         nullptr, Pp, Ss, qsum, rs,
                                         hs, nullptr);
    // 6) h1 @ mem_w2, final epilogue: out = RS*hm + P*acc + S*hs
    gemm_mma<4><<<grid1, 256, SMEM_GB>>>(h1, 0LL, wt6, wt6, nullptr, out, out, nullptr,
                                         hm, Pp, Ss, hs, rs,
                                         nullptr, nullptr);
}

// round 15
// speedup vs baseline: 2.1179x; 1.2191x over previous
#include <cuda_runtime.h>
#include <cuda_fp16.h>
#include <math.h>
#include <stdint.h>

// Problem sizes (fixed by the reference)
#define BB 8
#define LL 2048
#define DD 512
#define MT (BB*LL)          // 16384 rows
#define SZ ((long long)MT*DD)

// ---------------- scratch (device globals; no allocation allowed) ----------------
__device__ float  g_xct[MT*DD];       // conv output, tf32-rounded (q-path A)
__device__ __half g_xch[MT*DD];       // conv output fp16 (eta/alpha A + EPI2 aux)
__device__ __half g_h1h[2*MT*DD];     // fp16 gelu(xc@{eta,alpha}w1)
__device__ float  g_h1[MT*DD];        // tf32 gelu(mem stage1)
__device__ float  g_hm[MT*DD];        // q-gemm out, tf32-rounded
// accum layout: [0,MT) hs | [MT,MT+LL) eta | [MT+LL,MT+2LL) alpha |
//               [MT+2LL, 2MT+2LL) ss | [2MT+2LL, 3MT+2LL) sg
#define ACC_N (3*MT + 2*LL)
__device__ float  g_accum[ACC_N];
__device__ float  g_ps[2*LL];         // [0:LL) p,  [LL:2LL) s
__device__ float  g_qsum[MT];         // s_r * rowsum(hm_r)
__device__ float  g_rs[MT];           // per-row l2norm scale s_r
__device__ float  g_wt[7*DD*DD];      // tf32 weights (slots 4,5,6 used)
__device__ __half g_wth[4*DD*DD];     // fp16 weights (slots 0-3: eta/alpha w1,w2 ^T)

__device__ __forceinline__ float gelu_exact(float x) {
    return 0.5f * x * (1.0f + erff(x * 0.70710678118654752f));
}
__device__ __forceinline__ float sigm(float x) {
    return 1.0f / (1.0f + expf(-x));
}
__device__ __forceinline__ uint32_t tf32_bits(float x) {
    uint32_t u; asm("cvt.rna.tf32.f32 %0, %1;" : "=r"(u) : "f"(x)); return u;
}
__device__ __forceinline__ float tf32_round(float x) {
    return __uint_as_float(tf32_bits(x));
}
__device__ __forceinline__ uint32_t smem_u32(const void* p) {
    uint32_t a;
    asm("{ .reg .u64 t; cvta.to.shared.u64 t, %1; cvt.u32.u64 %0, t; }" : "=r"(a) : "l"(p));
    return a;
}

// ---------------- prep weights (+ z==8: zero accum) ----------------
// z 0-3 -> fp16 transposed into wth; z 4 (q_w copy), 5,6 (mem_w^T) -> tf32 into wt
__global__ void prep_weights(const float* __restrict__ ew1, const float* __restrict__ aw1,
                             const float* __restrict__ ew2, const float* __restrict__ aw2,
                             const float* __restrict__ qw,  const float* __restrict__ mw1,
                             const float* __restrict__ mw2, float* __restrict__ wt,
                             __half* __restrict__ wth, float* __restrict__ accum) {
    __shared__ float tile[32][33];
    int zi = blockIdx.z;
    int tx = threadIdx.x, ty = threadIdx.y;  // (32, 8)
    if (zi == 8) {
        int blk = blockIdx.y * 16 + blockIdx.x;
        int t = ty * 32 + tx;
        int idx = blk * 208 + t;
        if (t < 208 && idx < ACC_N) accum[idx] = 0.0f;
        return;
    }
    const float* src; bool tr = true;
    switch (zi) {
        case 0: src = ew1; break;
        case 1: src = aw1; break;
        case 2: src = ew2; break;
        case 3: src = aw2; break;
        case 4: src = qw; tr = false; break;
        case 5: src = mw1; break;
        default: src = mw2; break;
    }
    int bx = blockIdx.x * 32, by = blockIdx.y * 32;
    if (tr) {
        #pragma unroll
        for (int i = 0; i < 32; i += 8)
            tile[ty + i][tx] = src[(long long)(by + ty + i) * DD + bx + tx];
        __syncthreads();
        if (zi < 4) {
            __half* dst = wth + (long long)zi * DD * DD;
            #pragma unroll
            for (int i = 0; i < 32; i += 8)
                dst[(long long)(bx + ty + i) * DD + by + tx] = __float2half_rn(tile[tx][ty + i]);
        } else {
            float* dst = wt + (long long)zi * DD * DD;
            #pragma unroll
            for (int i = 0; i < 32; i += 8)
                dst[(long long)(bx + ty + i) * DD + by + tx] = tf32_round(tile[tx][ty + i]);
        }
    } else {
        float* dst = wt + (long long)zi * DD * DD;
        #pragma unroll
        for (int i = 0; i < 32; i += 8)
            dst[(long long)(by + ty + i) * DD + bx + tx] =
                tf32_round(src[(long long)(by + ty + i) * DD + bx + tx]);
    }
}

// ---------------- causal depthwise conv -> xct (tf32) + xch (fp16) ----------------
__global__ void conv_kernel(const float* __restrict__ x, const float* __restrict__ w,
                            const float* __restrict__ bias, float* __restrict__ xct,
                            __half* __restrict__ xch) {
    int idx = blockIdx.x * blockDim.x + threadIdx.x;
    if (idx >= MT * (DD/4)) return;
    int d4 = idx & 127;
    int r  = idx >> 7;
    int l  = r & (LL-1);
    int d  = d4 * 4;
    float4 out = *(const float4*)(bias + d);
    #pragma unroll
    for (int k = 0; k < 4; k++) {
        int li = l + k - 3;
        if (li >= 0) {
            float4 xv = *(const float4*)(x + (long long)(r + k - 3) * DD + d);
            out.x += xv.x * w[(d+0)*4 + k];
            out.y += xv.y * w[(d+1)*4 + k];
            out.z += xv.z * w[(d+2)*4 + k];
            out.w += xv.w * w[(d+3)*4 + k];
        }
    }
    long long off = (long long)r * DD + d;
    float4 rt = { tf32_round(out.x), tf32_round(out.y), tf32_round(out.z), tf32_round(out.w) };
    *(float4*)(xct + off) = rt;
    *(__half2*)(xch + off)     = __floats2half2_rn(out.x, out.y);
    *(__half2*)(xch + off + 2) = __floats2half2_rn(out.z, out.w);
}

// ---------------- scan (block 0) + row-norm finalize (blocks 1..16) ----------------
__global__ void scan_kernel(const float* __restrict__ red, float* __restrict__ PS,
                            const float* __restrict__ ss, const float* __restrict__ sg,
                            float* __restrict__ rs, float* __restrict__ qsum) {
    if (blockIdx.x > 0) {
        int r = (blockIdx.x - 1) * 1024 + threadIdx.x;
        float scale = 1.0f / fmaxf(sqrtf(ss[r]), 1e-12f);
        rs[r]   = scale;
        qsum[r] = sg[r] * scale;
        return;
    }
    __shared__ float Aa[2][LL];
    __shared__ float Bb[2][LL];
    const float inv = 1.0f / (float)(BB * DD);
    int t = threadIdx.x;  // 1024
    #pragma unroll
    for (int h = 0; h < 2; h++) {
        int e = t + h * 1024;
        Aa[0][e] = red[LL + e] * inv;        // alpha mean
        Bb[0][e] = -0.01f * red[e] * inv;    // -0.01 * eta mean
    }
    int cur = 0;
    for (int d = 1; d < LL; d <<= 1) {
        __syncthreads();
        #pragma unroll
        for (int h = 0; h < 2; h++) {
            int e = t + h * 1024;
            float A2 = Aa[cur][e], B2 = Bb[cur][e];
            if (e >= d) {
                float A1 = Aa[cur][e - d], B1 = Bb[cur][e - d];
                B2 = A2 * B1 + B2;
                A2 = A1 * A2;
            }
            Aa[cur ^ 1][e] = A2;
            Bb[cur ^ 1][e] = B2;
        }
        cur ^= 1;
    }
    __syncthreads();
    #pragma unroll
    for (int h = 0; h < 2; h++) {
        int e = t + h * 1024;
        PS[e]      = (e == 0) ? 1.0f : Aa[cur][e - 1];
        PS[LL + e] = (e == 0) ? 0.0f : Bb[cur][e - 1];
    }
}

// ================== tf32 GEMM (q-chain; proven R14 core) ==================
// EPI 0: C = tf32(acc); fused rownorm atomics red0[r]+=sum v^2, red1[r]+=sum v
// EPI 3: h = gelu(P[l]*RS[r]*acc + S[l]*vin[r]); C = tf32(h); red0[r] += sum h
// EPI 4: C = RS[r]*aux[r,c] + P[l]*acc + S[l]*vin[r]
#define SW 36
#define STG_WORDS (128*SW)
#define SMEM_GB (6*STG_WORDS*4)     // 110592 B

template<int EPI>
__global__ __launch_bounds__(256, 2)
void gemm_mma(const float* __restrict__ A,
              const float* __restrict__ Bt0,
              float* C0,
              const float* __restrict__ aux,
              const float* __restrict__ P, const float* __restrict__ S,
              const float* __restrict__ vin,
              const float* __restrict__ RS,
              float* red0, float* red1) {
    extern __shared__ uint32_t smemBuf[];
    const uint32_t sbase = smem_u32(smemBuf);

    const int tid  = threadIdx.x;
    const int lane = tid & 31, warp = tid >> 5;
    const int wm = warp >> 2, wn = warp & 3;
    const int qr = lane >> 2, qk = lane & 3;
    const int rowBase = blockIdx.y * 128;
    const int colBase = blockIdx.x * 128;
    const float* Ab = A;
    const float* Bt = Bt0;
    float* C        = C0;

    float acc[4][4][4];
    #pragma unroll
    for (int mf = 0; mf < 4; mf++)
        #pragma unroll
        for (int nf = 0; nf < 4; nf++)
            #pragma unroll
            for (int i = 0; i < 4; i++) acc[mf][nf][i] = 0.0f;

    const int lr = tid >> 3;
    const int lc = (tid & 7) * 4;

    auto issue = [&](int kc, int s) {
        const int k0 = kc * 32;
        const uint32_t abase = sbase + s * (STG_WORDS * 4);
        const uint32_t bbase = sbase + (3 + s) * (STG_WORDS * 4);
        #pragma unroll
        for (int i = 0; i < 4; i++) {
            int row = lr + i * 32;
            const float* ga = Ab + (long long)(rowBase + row) * DD + k0 + lc;
            const float* gb = Bt + (long long)(colBase + row) * DD + k0 + lc;
            asm volatile("cp.async.cg.shared.global [%0], [%1], 16;"
                :: "r"(abase + (row * SW + lc) * 4), "l"(__cvta_generic_to_global(ga)));
            asm volatile("cp.async.cg.shared.global [%0], [%1], 16;"
                :: "r"(bbase + (row * SW + lc) * 4), "l"(__cvta_generic_to_global(gb)));
        }
        asm volatile("cp.async.commit_group;" ::: "memory");
    };

    const uint32_t aoff = (uint32_t)(((lane & 15) * SW + (lane >> 4) * 4) * 4);
    const uint32_t boff = (uint32_t)((((lane & 7) + ((lane >> 4) << 3)) * SW
                                      + ((lane >> 3) & 1) * 4) * 4);
    const uint32_t aWarp = (uint32_t)(wm * 64) * SW * 4;
    const uint32_t bWarp = (uint32_t)(wn * 32) * SW * 4;

    auto compute = [&](int s) {
        const uint32_t aStg = sbase + s * (STG_WORDS * 4) + aWarp + aoff;
        const uint32_t bStg = sbase + (3 + s) * (STG_WORDS * 4) + bWarp + boff;
        #pragma unroll
        for (int ks = 0; ks < 4; ks++) {
            uint32_t a[4][4], b[4][2];
            #pragma unroll
            for (int mf = 0; mf < 4; mf++) {
                uint32_t addr = aStg + (uint32_t)((mf * 16 * SW + ks * 8) * 4);
                asm volatile("ldmatrix.sync.aligned.m8n8.x4.shared.b16 {%0,%1,%2,%3}, [%4];"
                    : "=r"(a[mf][0]), "=r"(a[mf][1]), "=r"(a[mf][2]), "=r"(a[mf][3])
                    : "r"(addr));
            }
            #pragma unroll
            for (int nfp = 0; nfp < 2; nfp++) {
                uint32_t addr = bStg + (uint32_t)((nfp * 16 * SW + ks * 8) * 4);
                asm volatile("ldmatrix.sync.aligned.m8n8.x4.shared.b16 {%0,%1,%2,%3}, [%4];"
                    : "=r"(b[2*nfp][0]), "=r"(b[2*nfp][1]),
                      "=r"(b[2*nfp+1][0]), "=r"(b[2*nfp+1][1])
                    : "r"(addr));
            }
            #pragma unroll
            for (int mf = 0; mf < 4; mf++)
                #pragma unroll
                for (int nf = 0; nf < 4; nf++)
                    asm volatile(
                        "mma.sync.aligned.m16n8k8.row.col.f32.tf32.tf32.f32 "
                        "{%0,%1,%2,%3}, {%4,%5,%6,%7}, {%8,%9}, {%0,%1,%2,%3};"
                        : "+f"(acc[mf][nf][0]), "+f"(acc[mf][nf][1]),
                          "+f"(acc[mf][nf][2]), "+f"(acc[mf][nf][3])
                        : "r"(a[mf][0]), "r"(a[mf][1]), "r"(a[mf][2]), "r"(a[mf][3]),
                          "r"(b[nf][0]), "r"(b[nf][1]));
        }
    };

    issue(0, 0);
    issue(1, 1);
    int s = 0;
    for (int kc = 0; kc < 15; kc++) {
        asm volatile("cp.async.wait_group 1;" ::: "memory");
        __syncthreads();
        compute(s);
        if (kc < 14) issue(kc + 2, (s + 2) % 3);
        s = (s + 1) % 3;
    }
    asm volatile("cp.async.wait_group 0;" ::: "memory");
    __syncthreads();
    compute(s);

    // ---- epilogue ----
    const int cBase = colBase + wn * 32 + 2 * qk;
    #pragma unroll
    for (int mf = 0; mf < 4; mf++) {
        #pragma unroll
        for (int half_ = 0; half_ < 2; half_++) {
            int r = rowBase + wm * 64 + mf * 16 + qr + half_ * 8;
            int l = r & (LL - 1);
            int ci = half_ * 2;
            float part = 0.0f, part2 = 0.0f;
            float pl = 0.f, sl = 0.f, vv = 0.f, rsv = 0.f;
            if (EPI == 3 || EPI == 4) { pl = P[l]; sl = S[l]; vv = vin[r]; rsv = RS[r]; }
            long long ro = (long long)r * DD;

            #pragma unroll
            for (int nf = 0; nf < 4; nf++) {
                float v0 = acc[mf][nf][ci], v1 = acc[mf][nf][ci + 1];
                long long off = ro + cBase + nf * 8;
                if (EPI == 0) {
                    float2 o = { tf32_round(v0), tf32_round(v1) };
                    part  += o.x * o.x + o.y * o.y;
                    part2 += o.x + o.y;
                    *(float2*)(C + off) = o;
                } else if (EPI == 3) {
                    float h0 = gelu_exact(pl * (rsv * v0) + sl * vv);
                    float h1 = gelu_exact(pl * (rsv * v1) + sl * vv);
                    part += h0 + h1;
                    float2 o = { tf32_round(h0), tf32_round(h1) };
                    *(float2*)(C + off) = o;
                } else if (EPI == 4) {
                    float2 a2 = *(const float2*)(aux + off);
                    float2 o = { rsv * a2.x + pl * v0 + sl * vv,
                                 rsv * a2.y + pl * v1 + sl * vv };
                    *(float2*)(C + off) = o;
                }
            }
            if (EPI == 0 || EPI == 3) {
                part += __shfl_xor_sync(0xffffffffu, part, 1);
                part += __shfl_xor_sync(0xffffffffu, part, 2);
                if (EPI == 0) {
                    part2 += __shfl_xor_sync(0xffffffffu, part2, 1);
                    part2 += __shfl_xor_sync(0xffffffffu, part2, 2);
                }
                if (qk == 0) {
                    if (EPI == 0) { atomicAdd(&red0[r], part); atomicAdd(&red1[r], part2); }
                    else          atomicAdd(&red0[r], part);
                }
            }
        }
    }
}

// ================== fp16 GEMM (eta/alpha branch; R5 core + peel fix) ==================
// A (rows x 512 f16), Bt (cols x 512 f16). CTA 128x128, BK=64, SW128-seg swizzle.
// EPI 1: C(f16) = gelu(acc)
// EPI 2: no store; atomicAdd red[(r&2047)] += sum_cols sigmoid(aux_h[r,c]+acc)
#define HSTG_BYTES 16384
#define SMEM_H (6 * HSTG_BYTES)     // 98304 B

template<int EPI>
__global__ __launch_bounds__(256, 2)
void gemm_h(const __half* __restrict__ A, long long Astride,
            const __half* __restrict__ Bt0, const __half* __restrict__ Bt1,
            void* C0v, void* C1v,
            const __half* __restrict__ aux,
            float* red0, float* red1) {
    extern __shared__ char smemH[];
    const uint32_t sbase = smem_u32(smemH);

    const int tid  = threadIdx.x;
    const int lane = tid & 31, warp = tid >> 5;
    const int wm = warp >> 2, wn = warp & 3;
    const int qr = lane >> 2, qk = lane & 3;
    const int rowBase = blockIdx.y * 128;
    const int colBase = blockIdx.x * 128;
    const int z = blockIdx.z;
    const __half* Ab = A + (long long)z * Astride;
    const __half* Bt = z ? Bt1 : Bt0;

    float acc[4][4][4];
    #pragma unroll
    for (int mf = 0; mf < 4; mf++)
        #pragma unroll
        for (int nf = 0; nf < 4; nf++)
            #pragma unroll
            for (int i = 0; i < 4; i++) acc[mf][nf][i] = 0.0f;

    auto issue = [&](int kc, int s) {
        const int k0 = kc * 64;
        const uint32_t abase = sbase + s * HSTG_BYTES;
        const uint32_t bbase = sbase + (3 + s) * HSTG_BYTES;
        #pragma unroll
        for (int i = 0; i < 4; i++) {
            int li = i * 256 + tid;
            int row = li >> 3, seg = li & 7;
            const __half* ga = Ab + (long long)(rowBase + row) * DD + k0 + seg * 8;
            const __half* gb = Bt + (long long)(colBase + row) * DD + k0 + seg * 8;
            uint32_t soff = row * 128 + ((seg ^ (row & 7)) << 4);
            asm volatile("cp.async.cg.shared.global [%0], [%1], 16;"
                :: "r"(abase + soff), "l"(__cvta_generic_to_global(ga)));
            asm volatile("cp.async.cg.shared.global [%0], [%1], 16;"
                :: "r"(bbase + soff), "l"(__cvta_generic_to_global(gb)));
        }
        asm volatile("cp.async.commit_group;" ::: "memory");
    };

    const int aRow = wm * 64 + (lane & 15);
    const int aSegH = (lane & 16) ? 1 : 0;
    const int bRow = wn * 32 + (lane & 7) + ((lane & 16) ? 8 : 0);
    const int bSegH = (lane & 8) ? 1 : 0;

    auto compute = [&](int s) {
        const uint32_t aStg = sbase + s * HSTG_BYTES;
        const uint32_t bStg = sbase + (3 + s) * HSTG_BYTES;
        #pragma unroll
        for (int ks = 0; ks < 4; ks++) {
            uint32_t a[4][4], b[2][4];
            #pragma unroll
            for (int mf = 0; mf < 4; mf++) {
                int row = aRow + mf * 16;
                int seg = ks * 2 + aSegH;
                uint32_t addr = aStg + row * 128 + (((seg ^ (row & 7))) << 4);
                asm volatile("ldmatrix.sync.aligned.m8n8.x4.shared.b16 {%0,%1,%2,%3}, [%4];"
                    : "=r"(a[mf][0]), "=r"(a[mf][1]), "=r"(a[mf][2]), "=r"(a[mf][3])
                    : "r"(addr));
            }
            #pragma unroll
            for (int nfp = 0; nfp < 2; nfp++) {
                int row = bRow + nfp * 16;
                int seg = ks * 2 + bSegH;
                uint32_t addr = bStg + row * 128 + (((seg ^ (row & 7))) << 4);
                asm volatile("ldmatrix.sync.aligned.m8n8.x4.shared.b16 {%0,%1,%2,%3}, [%4];"
                    : "=r"(b[nfp][0]), "=r"(b[nfp][1]), "=r"(b[nfp][2]), "=r"(b[nfp][3])
                    : "r"(addr));
            }
            #pragma unroll
            for (int mf = 0; mf < 4; mf++)
                #pragma unroll
                for (int nf = 0; nf < 4; nf++) {
                    const uint32_t* bb = &b[nf >> 1][(nf & 1) * 2];
                    asm volatile(
                        "mma.sync.aligned.m16n8k16.row.col.f32.f16.f16.f32 "
                        "{%0,%1,%2,%3}, {%4,%5,%6,%7}, {%8,%9}, {%0,%1,%2,%3};"
                        : "+f"(acc[mf][nf][0]), "+f"(acc[mf][nf][1]),
                          "+f"(acc[mf][nf][2]), "+f"(acc[mf][nf][3])
                        : "r"(a[mf][0]), "r"(a[mf][1]), "r"(a[mf][2]), "r"(a[mf][3]),
                          "r"(bb[0]), "r"(bb[1]));
                }
        }
    };

    issue(0, 0);
    issue(1, 1);
    int s = 0;
    for (int kc = 0; kc < 7; kc++) {
        asm volatile("cp.async.wait_group 1;" ::: "memory");
        __syncthreads();
        compute(s);
        if (kc < 6) issue(kc + 2, (s + 2) % 3);
        s = (s + 1) % 3;
    }
    asm volatile("cp.async.wait_group 0;" ::: "memory");
    __syncthreads();
    compute(s);

    // ---- epilogue ----
    float* red = z ? red1 : red0;
    const int cBase = colBase + wn * 32 + 2 * qk;
    __half* Ch = (__half*)(z ? C1v : C0v);

    #pragma unroll
    for (int mf = 0; mf < 4; mf++) {
        #pragma unroll
        for (int half_ = 0; half_ < 2; half_++) {
            int r = rowBase + wm * 64 + mf * 16 + qr + half_ * 8;
            int l = r & (LL - 1);
            int ci = half_ * 2;
            float part = 0.0f;
            long long ro = (long long)r * DD;

            #pragma unroll
            for (int nf = 0; nf < 4; nf++) {
                float v0 = acc[mf][nf][ci], v1 = acc[mf][nf][ci + 1];
                long long off = ro + cBase + nf * 8;
                if (EPI == 1) {
                    *(__half2*)(Ch + off) = __floats2half2_rn(gelu_exact(v0), gelu_exact(v1));
                } else {  // EPI == 2
                    float2 a2 = __half22float2(*(const __half2*)(aux + off));
                    part += sigm(a2.x + v0) + sigm(a2.y + v1);
                }
            }
            if (EPI == 2) {
                part += __shfl_xor_sync(0xffffffffu, part, 1);
                part += __shfl_xor_sync(0xffffffffu, part, 2);
                if (qk == 0) atomicAdd(&red[l], part);
            }
        }
    }
}

// ---------------- launcher ----------------
extern "C" void kernel_launch(void* const* d_in, const int* in_sizes, int n_in,
                              void* d_out, int out_size) {
    const float* x        = (const float*)d_in[0];
    const float* conv_w   = (const float*)d_in[1];
    const float* conv_b   = (const float*)d_in[2];
    const float* q_w      = (const float*)d_in[3];
    const float* mem_w1   = (const float*)d_in[4];
    const float* mem_w2   = (const float*)d_in[5];
    const float* eta_w1   = (const float*)d_in[6];
    const float* eta_w2   = (const float*)d_in[7];
    const float* alpha_w1 = (const float*)d_in[8];
    const float* alpha_w2 = (const float*)d_in[9];
    float* out = (float*)d_out;

    float *xct, *h1, *hm, *accum, *ps, *qsum, *rs, *wt;
    __half *xch, *h1h, *wth;
    cudaGetSymbolAddress((void**)&xct,   g_xct);
    cudaGetSymbolAddress((void**)&xch,   g_xch);
    cudaGetSymbolAddress((void**)&h1h,   g_h1h);
    cudaGetSymbolAddress((void**)&h1,    g_h1);
    cudaGetSymbolAddress((void**)&hm,    g_hm);
    cudaGetSymbolAddress((void**)&accum, g_accum);
    cudaGetSymbolAddress((void**)&ps,    g_ps);
    cudaGetSymbolAddress((void**)&qsum,  g_qsum);
    cudaGetSymbolAddress((void**)&rs,    g_rs);
    cudaGetSymbolAddress((void**)&wt,    g_wt);
    cudaGetSymbolAddress((void**)&wth,   g_wth);

    float* hs        = accum;                 // [MT]
    float* eta_sum   = accum + MT;            // [LL]
    float* alpha_sum = accum + MT + LL;       // [LL]
    float* ssA       = accum + MT + 2*LL;     // [MT]
    float* sgA       = accum + 2*MT + 2*LL;   // [MT]
    float* Pp = ps;
    float* Ss = ps + LL;

    static bool attr_done = false;
    if (!attr_done) {
        cudaFuncSetAttribute(gemm_mma<0>, cudaFuncAttributeMaxDynamicSharedMemorySize, SMEM_GB);
        cudaFuncSetAttribute(gemm_mma<3>, cudaFuncAttributeMaxDynamicSharedMemorySize, SMEM_GB);
        cudaFuncSetAttribute(gemm_mma<4>, cudaFuncAttributeMaxDynamicSharedMemorySize, SMEM_GB);
        cudaFuncSetAttribute(gemm_h<1>,  cudaFuncAttributeMaxDynamicSharedMemorySize, SMEM_H);
        cudaFuncSetAttribute(gemm_h<2>,  cudaFuncAttributeMaxDynamicSharedMemorySize, SMEM_H);
        attr_done = true;
    }

    // 0) prep weights (fp16 slots 0-3, tf32 slots 4-6) + zero accum (z==8)
    prep_weights<<<dim3(16, 16, 9), dim3(32, 8)>>>(eta_w1, alpha_w1, eta_w2, alpha_w2,
                                                   q_w, mem_w1, mem_w2, wt, wth, accum);
    // 1) conv -> xct (tf32) + xch (fp16)
    conv_kernel<<<(MT * (DD/4) + 255) / 256, 256>>>(x, conv_w, conv_b, xct, xch);

    dim3 grid2(DD / 128, MT / 128, 2);
    dim3 grid1(DD / 128, MT / 128, 1);
    __half* wh0 = wth + 0LL * DD * DD;  // eta_w1^T   (fp16)
    __half* wh1 = wth + 1LL * DD * DD;  // alpha_w1^T (fp16)
    __half* wh2 = wth + 2LL * DD * DD;  // eta_w2^T   (fp16)
    __half* wh3 = wth + 3LL * DD * DD;  // alpha_w2^T (fp16)
    float* wt4 = wt + 4LL * DD * DD;    // q_w     (tf32)
    float* wt5 = wt + 5LL * DD * DD;    // mem_w1^T(tf32)
    float* wt6 = wt + 6LL * DD * DD;    // mem_w2^T(tf32)

    // 2) fp16: xch @ {eta_w1, alpha_w1} -> fp16 gelu -> h1h[z]
    gemm_h<1><<<grid2, 256, SMEM_H>>>(xch, 0LL, wh0, wh1, h1h, h1h + SZ,
                                      nullptr, nullptr, nullptr);
    // 3) tf32: xct @ q_w^T -> hm (tf32) + fused rownorm atomics
    gemm_mma<0><<<grid1, 256, SMEM_GB>>>(xct, wt4, hm,
                                         nullptr, nullptr, nullptr, nullptr, nullptr,
                                         ssA, sgA);
    // 4) fp16: h1h[z] @ {eta_w2, alpha_w2} -> sigmoid(xch + .) -> per-l sums
    gemm_h<2><<<grid2, 256, SMEM_H>>>(h1h, SZ, wh2, wh3, nullptr, nullptr,
                                      xch, eta_sum, alpha_sum);
    // 5) scan (block 0) + rownorm finalize (blocks 1..16)
    scan_kernel<<<17, 1024>>>(eta_sum, ps, ssA, sgA, rs, qsum);
    // 6) tf32: hm @ mem_w1, gelu(P*RS*acc + S*qsum) -> h1, hs
    gemm_mma<3><<<grid1, 256, SMEM_GB>>>(hm, wt5, h1,
                                         nullptr, Pp, Ss, qsum, rs,
                                         hs, nullptr);
    // 7) tf32: h1 @ mem_w2, out = RS*hm + P*acc + S*hs
    gemm_mma<4><<<grid1, 256, SMEM_GB>>>(h1, wt6, out,
                                         hm, Pp, Ss, hs, rs,
                                         nullptr, nullptr);
}

// round 16
// speedup vs baseline: 2.4293x; 1.1470x over previous
#include <cuda_runtime.h>
#include <cuda_fp16.h>
#include <math.h>
#include <stdint.h>

// Problem sizes (fixed by the reference)
#define BB 8
#define LL 2048
#define DD 512
#define MT (BB*LL)          // 16384 rows
#define SZ ((long long)MT*DD)

// ---------------- scratch (device globals; no allocation allowed) ----------------
__device__ float  g_xct[MT*DD];       // conv output, tf32-rounded (q-gemm A)
__device__ __half g_xch[MT*DD];       // conv output fp16 (eta/alpha A + EPI2 aux)
__device__ __half g_h1h[2*MT*DD];     // fp16 gelu buffers (eta/alpha; slot0 reused by mem h)
__device__ float  g_hm[MT*DD];        // q-gemm out, tf32 (aux for final epilogue)
__device__ __half g_hmh[MT*DD];       // q-gemm out fp16 (A of mem stage1)
// accum layout: [0,MT) hs | [MT,MT+LL) eta | [MT+LL,MT+2LL) alpha |
//               [MT+2LL, 2MT+2LL) ss | [2MT+2LL, 3MT+2LL) sg
#define ACC_N (3*MT + 2*LL)
__device__ float  g_accum[ACC_N];
__device__ float  g_ps[2*LL];         // [0:LL) p,  [LL:2LL) s
__device__ float  g_qsum[MT];         // s_r * rowsum(hm_r)
__device__ float  g_rs[MT];           // per-row l2norm scale s_r
__device__ float  g_wtq[DD*DD];       // q_w tf32
__device__ __half g_wth[6*DD*DD];     // fp16 weights: eta_w1^T, alpha_w1^T, eta_w2^T,
                                      //               alpha_w2^T, mem_w1^T, mem_w2^T

__device__ __forceinline__ float gelu_exact(float x) {
    return 0.5f * x * (1.0f + erff(x * 0.70710678118654752f));
}
__device__ __forceinline__ float sigm(float x) {
    return 1.0f / (1.0f + expf(-x));
}
__device__ __forceinline__ uint32_t tf32_bits(float x) {
    uint32_t u; asm("cvt.rna.tf32.f32 %0, %1;" : "=r"(u) : "f"(x)); return u;
}
__device__ __forceinline__ float tf32_round(float x) {
    return __uint_as_float(tf32_bits(x));
}
__device__ __forceinline__ uint32_t smem_u32(const void* p) {
    uint32_t a;
    asm("{ .reg .u64 t; cvta.to.shared.u64 t, %1; cvt.u32.u64 %0, t; }" : "=r"(a) : "l"(p));
    return a;
}

// ---------------- prep weights (+ z==7: zero accum) ----------------
// z: 0 eta_w1^T, 1 alpha_w1^T, 2 eta_w2^T, 3 alpha_w2^T -> wth slots 0-3 (fp16)
//    4 q_w (copy, tf32 -> wtq), 5 mem_w1^T -> wth slot 4, 6 mem_w2^T -> wth slot 5
__global__ void prep_weights(const float* __restrict__ ew1, const float* __restrict__ aw1,
                             const float* __restrict__ ew2, const float* __restrict__ aw2,
                             const float* __restrict__ qw,  const float* __restrict__ mw1,
                             const float* __restrict__ mw2, float* __restrict__ wtq,
                             __half* __restrict__ wth, float* __restrict__ accum) {
    __shared__ float tile[32][33];
    int zi = blockIdx.z;
    int tx = threadIdx.x, ty = threadIdx.y;  // (32, 8)
    if (zi == 7) {
        int blk = blockIdx.y * 16 + blockIdx.x;
        int t = ty * 32 + tx;
        int idx = blk * 208 + t;
        if (t < 208 && idx < ACC_N) accum[idx] = 0.0f;
        return;
    }
    int bx = blockIdx.x * 32, by = blockIdx.y * 32;
    if (zi == 4) {
        #pragma unroll
        for (int i = 0; i < 32; i += 8)
            wtq[(long long)(by + ty + i) * DD + bx + tx] =
                tf32_round(qw[(long long)(by + ty + i) * DD + bx + tx]);
        return;
    }
    const float* src;
    int slot;
    switch (zi) {
        case 0: src = ew1; slot = 0; break;
        case 1: src = aw1; slot = 1; break;
        case 2: src = ew2; slot = 2; break;
        case 3: src = aw2; slot = 3; break;
        case 5: src = mw1; slot = 4; break;
        default: src = mw2; slot = 5; break;
    }
    #pragma unroll
    for (int i = 0; i < 32; i += 8)
        tile[ty + i][tx] = src[(long long)(by + ty + i) * DD + bx + tx];
    __syncthreads();
    __half* dst = wth + (long long)slot * DD * DD;
    #pragma unroll
    for (int i = 0; i < 32; i += 8)
        dst[(long long)(bx + ty + i) * DD + by + tx] = __float2half_rn(tile[tx][ty + i]);
}

// ---------------- causal depthwise conv -> xct (tf32) + xch (fp16) ----------------
__global__ void conv_kernel(const float* __restrict__ x, const float* __restrict__ w,
                            const float* __restrict__ bias, float* __restrict__ xct,
                            __half* __restrict__ xch) {
    int idx = blockIdx.x * blockDim.x + threadIdx.x;
    if (idx >= MT * (DD/4)) return;
    int d4 = idx & 127;
    int r  = idx >> 7;
    int l  = r & (LL-1);
    int d  = d4 * 4;
    float4 out = *(const float4*)(bias + d);
    #pragma unroll
    for (int k = 0; k < 4; k++) {
        int li = l + k - 3;
        if (li >= 0) {
            float4 xv = *(const float4*)(x + (long long)(r + k - 3) * DD + d);
            out.x += xv.x * w[(d+0)*4 + k];
            out.y += xv.y * w[(d+1)*4 + k];
            out.z += xv.z * w[(d+2)*4 + k];
            out.w += xv.w * w[(d+3)*4 + k];
        }
    }
    long long off = (long long)r * DD + d;
    float4 rt = { tf32_round(out.x), tf32_round(out.y), tf32_round(out.z), tf32_round(out.w) };
    *(float4*)(xct + off) = rt;
    *(__half2*)(xch + off)     = __floats2half2_rn(out.x, out.y);
    *(__half2*)(xch + off + 2) = __floats2half2_rn(out.z, out.w);
}

// ---------------- scan (block 0) + row-norm finalize (blocks 1..16) ----------------
__global__ void scan_kernel(const float* __restrict__ red, float* __restrict__ PS,
                            const float* __restrict__ ss, const float* __restrict__ sg,
                            float* __restrict__ rs, float* __restrict__ qsum) {
    if (blockIdx.x > 0) {
        int r = (blockIdx.x - 1) * 1024 + threadIdx.x;
        float scale = 1.0f / fmaxf(sqrtf(ss[r]), 1e-12f);
        rs[r]   = scale;
        qsum[r] = sg[r] * scale;
        return;
    }
    __shared__ float Aa[2][LL];
    __shared__ float Bb[2][LL];
    const float inv = 1.0f / (float)(BB * DD);
    int t = threadIdx.x;  // 1024
    #pragma unroll
    for (int h = 0; h < 2; h++) {
        int e = t + h * 1024;
        Aa[0][e] = red[LL + e] * inv;        // alpha mean
        Bb[0][e] = -0.01f * red[e] * inv;    // -0.01 * eta mean
    }
    int cur = 0;
    for (int d = 1; d < LL; d <<= 1) {
        __syncthreads();
        #pragma unroll
        for (int h = 0; h < 2; h++) {
            int e = t + h * 1024;
            float A2 = Aa[cur][e], B2 = Bb[cur][e];
            if (e >= d) {
                float A1 = Aa[cur][e - d], B1 = Bb[cur][e - d];
                B2 = A2 * B1 + B2;
                A2 = A1 * A2;
            }
            Aa[cur ^ 1][e] = A2;
            Bb[cur ^ 1][e] = B2;
        }
        cur ^= 1;
    }
    __syncthreads();
    #pragma unroll
    for (int h = 0; h < 2; h++) {
        int e = t + h * 1024;
        PS[e]      = (e == 0) ? 1.0f : Aa[cur][e - 1];
        PS[LL + e] = (e == 0) ? 0.0f : Bb[cur][e - 1];
    }
}

// ================== tf32 GEMM (q-gemm only; proven core) ==================
// EPI 0: C = tf32(acc) + fp16 copy Ch; rownorm atomics red0[r]+=sum v^2, red1[r]+=sum v
#define SW 36
#define STG_WORDS (128*SW)
#define SMEM_GB (6*STG_WORDS*4)     // 110592 B

__global__ __launch_bounds__(256, 2)
void gemm_q(const float* __restrict__ A,
            const float* __restrict__ Bt0,
            float* C0, __half* Ch,
            float* red0, float* red1) {
    extern __shared__ uint32_t smemBuf[];
    const uint32_t sbase = smem_u32(smemBuf);

    const int tid  = threadIdx.x;
    const int lane = tid & 31, warp = tid >> 5;
    const int wm = warp >> 2, wn = warp & 3;
    const int qr = lane >> 2, qk = lane & 3;
    const int rowBase = blockIdx.y * 128;
    const int colBase = blockIdx.x * 128;

    float acc[4][4][4];
    #pragma unroll
    for (int mf = 0; mf < 4; mf++)
        #pragma unroll
        for (int nf = 0; nf < 4; nf++)
            #pragma unroll
            for (int i = 0; i < 4; i++) acc[mf][nf][i] = 0.0f;

    const int lr = tid >> 3;
    const int lc = (tid & 7) * 4;

    auto issue = [&](int kc, int s) {
        const int k0 = kc * 32;
        const uint32_t abase = sbase + s * (STG_WORDS * 4);
        const uint32_t bbase = sbase + (3 + s) * (STG_WORDS * 4);
        #pragma unroll
        for (int i = 0; i < 4; i++) {
            int row = lr + i * 32;
            const float* ga = A + (long long)(rowBase + row) * DD + k0 + lc;
            const float* gb = Bt0 + (long long)(colBase + row) * DD + k0 + lc;
            asm volatile("cp.async.cg.shared.global [%0], [%1], 16;"
                :: "r"(abase + (row * SW + lc) * 4), "l"(__cvta_generic_to_global(ga)));
            asm volatile("cp.async.cg.shared.global [%0], [%1], 16;"
                :: "r"(bbase + (row * SW + lc) * 4), "l"(__cvta_generic_to_global(gb)));
        }
        asm volatile("cp.async.commit_group;" ::: "memory");
    };

    const uint32_t aoff = (uint32_t)(((lane & 15) * SW + (lane >> 4) * 4) * 4);
    const uint32_t boff = (uint32_t)((((lane & 7) + ((lane >> 4) << 3)) * SW
                                      + ((lane >> 3) & 1) * 4) * 4);
    const uint32_t aWarp = (uint32_t)(wm * 64) * SW * 4;
    const uint32_t bWarp = (uint32_t)(wn * 32) * SW * 4;

    auto compute = [&](int s) {
        const uint32_t aStg = sbase + s * (STG_WORDS * 4) + aWarp + aoff;
        const uint32_t bStg = sbase + (3 + s) * (STG_WORDS * 4) + bWarp + boff;
        #pragma unroll
        for (int ks = 0; ks < 4; ks++) {
            uint32_t a[4][4], b[4][2];
            #pragma unroll
            for (int mf = 0; mf < 4; mf++) {
                uint32_t addr = aStg + (uint32_t)((mf * 16 * SW + ks * 8) * 4);
                asm volatile("ldmatrix.sync.aligned.m8n8.x4.shared.b16 {%0,%1,%2,%3}, [%4];"
                    : "=r"(a[mf][0]), "=r"(a[mf][1]), "=r"(a[mf][2]), "=r"(a[mf][3])
                    : "r"(addr));
            }
            #pragma unroll
            for (int nfp = 0; nfp < 2; nfp++) {
                uint32_t addr = bStg + (uint32_t)((nfp * 16 * SW + ks * 8) * 4);
                asm volatile("ldmatrix.sync.aligned.m8n8.x4.shared.b16 {%0,%1,%2,%3}, [%4];"
                    : "=r"(b[2*nfp][0]), "=r"(b[2*nfp][1]),
                      "=r"(b[2*nfp+1][0]), "=r"(b[2*nfp+1][1])
                    : "r"(addr));
            }
            #pragma unroll
            for (int mf = 0; mf < 4; mf++)
                #pragma unroll
                for (int nf = 0; nf < 4; nf++)
                    asm volatile(
                        "mma.sync.aligned.m16n8k8.row.col.f32.tf32.tf32.f32 "
                        "{%0,%1,%2,%3}, {%4,%5,%6,%7}, {%8,%9}, {%0,%1,%2,%3};"
                        : "+f"(acc[mf][nf][0]), "+f"(acc[mf][nf][1]),
                          "+f"(acc[mf][nf][2]), "+f"(acc[mf][nf][3])
                        : "r"(a[mf][0]), "r"(a[mf][1]), "r"(a[mf][2]), "r"(a[mf][3]),
                          "r"(b[nf][0]), "r"(b[nf][1]));
        }
    };

    issue(0, 0);
    issue(1, 1);
    int s = 0;
    for (int kc = 0; kc < 15; kc++) {
        asm volatile("cp.async.wait_group 1;" ::: "memory");
        __syncthreads();
        compute(s);
        if (kc < 14) issue(kc + 2, (s + 2) % 3);
        s = (s + 1) % 3;
    }
    asm volatile("cp.async.wait_group 0;" ::: "memory");
    __syncthreads();
    compute(s);

    const int cBase = colBase + wn * 32 + 2 * qk;
    #pragma unroll
    for (int mf = 0; mf < 4; mf++) {
        #pragma unroll
        for (int half_ = 0; half_ < 2; half_++) {
            int r = rowBase + wm * 64 + mf * 16 + qr + half_ * 8;
            int ci = half_ * 2;
            float part = 0.0f, part2 = 0.0f;
            long long ro = (long long)r * DD;
            #pragma unroll
            for (int nf = 0; nf < 4; nf++) {
                float v0 = acc[mf][nf][ci], v1 = acc[mf][nf][ci + 1];
                long long off = ro + cBase + nf * 8;
                float2 o = { tf32_round(v0), tf32_round(v1) };
                part  += o.x * o.x + o.y * o.y;
                part2 += o.x + o.y;
                *(float2*)(C0 + off) = o;
                *(__half2*)(Ch + off) = __floats2half2_rn(o.x, o.y);
            }
            part += __shfl_xor_sync(0xffffffffu, part, 1);
            part += __shfl_xor_sync(0xffffffffu, part, 2);
            part2 += __shfl_xor_sync(0xffffffffu, part2, 1);
            part2 += __shfl_xor_sync(0xffffffffu, part2, 2);
            if (qk == 0) { atomicAdd(&red0[r], part); atomicAdd(&red1[r], part2); }
        }
    }
}

// ================== fp16 GEMM (race-fixed; 4 epilogues) ==================
// EPI 1: C(f16) = gelu(acc)                                [eta/alpha stage1, z batched]
// EPI 2: atomicAdd red[(r&2047)] += sum sigmoid(aux_h + acc) [eta/alpha stage2]
// EPI 3: h = gelu(P[l]*RS[r]*acc + S[l]*vin[r]); C(f16)=h; red0[r] += sum h
// EPI 4: C(f32) = RS[r]*auxf + P[l]*acc + S[l]*vin[r]
#define HSTG_BYTES 16384
#define SMEM_H (6 * HSTG_BYTES)     // 98304 B

template<int EPI>
__global__ __launch_bounds__(256, 2)
void gemm_h(const __half* __restrict__ A, long long Astride,
            const __half* __restrict__ Bt0, const __half* __restrict__ Bt1,
            void* C0v, void* C1v,
            const __half* __restrict__ aux,
            const float* __restrict__ auxf,
            const float* __restrict__ P, const float* __restrict__ S,
            const float* __restrict__ vin, const float* __restrict__ RS,
            float* red0, float* red1) {
    extern __shared__ char smemH[];
    const uint32_t sbase = smem_u32(smemH);

    const int tid  = threadIdx.x;
    const int lane = tid & 31, warp = tid >> 5;
    const int wm = warp >> 2, wn = warp & 3;
    const int qr = lane >> 2, qk = lane & 3;
    const int rowBase = blockIdx.y * 128;
    const int colBase = blockIdx.x * 128;
    const int z = blockIdx.z;
    const __half* Ab = A + (long long)z * Astride;
    const __half* Bt = z ? Bt1 : Bt0;

    float acc[4][4][4];
    #pragma unroll
    for (int mf = 0; mf < 4; mf++)
        #pragma unroll
        for (int nf = 0; nf < 4; nf++)
            #pragma unroll
            for (int i = 0; i < 4; i++) acc[mf][nf][i] = 0.0f;

    auto issue = [&](int kc, int s) {
        const int k0 = kc * 64;
        const uint32_t abase = sbase + s * HSTG_BYTES;
        const uint32_t bbase = sbase + (3 + s) * HSTG_BYTES;
        #pragma unroll
        for (int i = 0; i < 4; i++) {
            int li = i * 256 + tid;
            int row = li >> 3, seg = li & 7;
            const __half* ga = Ab + (long long)(rowBase + row) * DD + k0 + seg * 8;
            const __half* gb = Bt + (long long)(colBase + row) * DD + k0 + seg * 8;
            uint32_t soff = row * 128 + ((seg ^ (row & 7)) << 4);
            asm volatile("cp.async.cg.shared.global [%0], [%1], 16;"
                :: "r"(abase + soff), "l"(__cvta_generic_to_global(ga)));
            asm volatile("cp.async.cg.shared.global [%0], [%1], 16;"
                :: "r"(bbase + soff), "l"(__cvta_generic_to_global(gb)));
        }
        asm volatile("cp.async.commit_group;" ::: "memory");
    };

    const int aRow = wm * 64 + (lane & 15);
    const int aSegH = (lane & 16) ? 1 : 0;
    const int bRow = wn * 32 + (lane & 7) + ((lane & 16) ? 8 : 0);
    const int bSegH = (lane & 8) ? 1 : 0;

    auto compute = [&](int s) {
        const uint32_t aStg = sbase + s * HSTG_BYTES;
        const uint32_t bStg = sbase + (3 + s) * HSTG_BYTES;
        #pragma unroll
        for (int ks = 0; ks < 4; ks++) {
            uint32_t a[4][4], b[2][4];
            #pragma unroll
            for (int mf = 0; mf < 4; mf++) {
                int row = aRow + mf * 16;
                int seg = ks * 2 + aSegH;
                uint32_t addr = aStg + row * 128 + (((seg ^ (row & 7))) << 4);
                asm volatile("ldmatrix.sync.aligned.m8n8.x4.shared.b16 {%0,%1,%2,%3}, [%4];"
                    : "=r"(a[mf][0]), "=r"(a[mf][1]), "=r"(a[mf][2]), "=r"(a[mf][3])
                    : "r"(addr));
            }
            #pragma unroll
            for (int nfp = 0; nfp < 2; nfp++) {
                int row = bRow + nfp * 16;
                int seg = ks * 2 + bSegH;
                uint32_t addr = bStg + row * 128 + (((seg ^ (row & 7))) << 4);
                asm volatile("ldmatrix.sync.aligned.m8n8.x4.shared.b16 {%0,%1,%2,%3}, [%4];"
                    : "=r"(b[nfp][0]), "=r"(b[nfp][1]), "=r"(b[nfp][2]), "=r"(b[nfp][3])
                    : "r"(addr));
            }
            #pragma unroll
            for (int mf = 0; mf < 4; mf++)
                #pragma unroll
                for (int nf = 0; nf < 4; nf++) {
                    const uint32_t* bb = &b[nf >> 1][(nf & 1) * 2];
                    asm volatile(
                        "mma.sync.aligned.m16n8k16.row.col.f32.f16.f16.f32 "
                        "{%0,%1,%2,%3}, {%4,%5,%6,%7}, {%8,%9}, {%0,%1,%2,%3};"
                        : "+f"(acc[mf][nf][0]), "+f"(acc[mf][nf][1]),
                          "+f"(acc[mf][nf][2]), "+f"(acc[mf][nf][3])
                        : "r"(a[mf][0]), "r"(a[mf][1]), "r"(a[mf][2]), "r"(a[mf][3]),
                          "r"(bb[0]), "r"(bb[1]));
                }
        }
    };

    issue(0, 0);
    issue(1, 1);
    int s = 0;
    for (int kc = 0; kc < 7; kc++) {
        asm volatile("cp.async.wait_group 1;" ::: "memory");
        __syncthreads();
        compute(s);
        if (kc < 6) issue(kc + 2, (s + 2) % 3);
        s = (s + 1) % 3;
    }
    asm volatile("cp.async.wait_group 0;" ::: "memory");
    __syncthreads();
    compute(s);

    // ---- epilogue ----
    float* red = (EPI == 2) ? (z ? red1 : red0) : red0;
    const int cBase = colBase + wn * 32 + 2 * qk;
    __half* Ch = (__half*)(z ? C1v : C0v);
    float*  Cf = (float*)C0v;

    #pragma unroll
    for (int mf = 0; mf < 4; mf++) {
        #pragma unroll
        for (int half_ = 0; half_ < 2; half_++) {
            int r = rowBase + wm * 64 + mf * 16 + qr + half_ * 8;
            int l = r & (LL - 1);
            int ci = half_ * 2;
            float part = 0.0f;
            float pl = 0.f, sl = 0.f, vv = 0.f, rsv = 0.f;
            if (EPI == 3 || EPI == 4) { pl = P[l]; sl = S[l]; vv = vin[r]; rsv = RS[r]; }
            long long ro = (long long)r * DD;

            #pragma unroll
            for (int nf = 0; nf < 4; nf++) {
                float v0 = acc[mf][nf][ci], v1 = acc[mf][nf][ci + 1];
                long long off = ro + cBase + nf * 8;
                if (EPI == 1) {
                    *(__half2*)(Ch + off) = __floats2half2_rn(gelu_exact(v0), gelu_exact(v1));
                } else if (EPI == 2) {
                    float2 a2 = __half22float2(*(const __half2*)(aux + off));
                    part += sigm(a2.x + v0) + sigm(a2.y + v1);
                } else if (EPI == 3) {
                    float h0 = gelu_exact(pl * (rsv * v0) + sl * vv);
                    float h1 = gelu_exact(pl * (rsv * v1) + sl * vv);
                    part += h0 + h1;
                    *(__half2*)(Ch + off) = __floats2half2_rn(h0, h1);
                } else {  // EPI == 4
                    float2 a2 = *(const float2*)(auxf + off);
                    float2 o = { rsv * a2.x + pl * v0 + sl * vv,
                                 rsv * a2.y + pl * v1 + sl * vv };
                    *(float2*)(Cf + off) = o;
                }
            }
            if (EPI == 2 || EPI == 3) {
                part += __shfl_xor_sync(0xffffffffu, part, 1);
                part += __shfl_xor_sync(0xffffffffu, part, 2);
                if (qk == 0) {
                    if (EPI == 2) atomicAdd(&red[l], part);
                    else          atomicAdd(&red0[r], part);
                }
            }
        }
    }
}

// ---------------- launcher ----------------
extern "C" void kernel_launch(void* const* d_in, const int* in_sizes, int n_in,
                              void* d_out, int out_size) {
    const float* x        = (const float*)d_in[0];
    const float* conv_w   = (const float*)d_in[1];
    const float* conv_b   = (const float*)d_in[2];
    const float* q_w      = (const float*)d_in[3];
    const float* mem_w1   = (const float*)d_in[4];
    const float* mem_w2   = (const float*)d_in[5];
    const float* eta_w1   = (const float*)d_in[6];
    const float* eta_w2   = (const float*)d_in[7];
    const float* alpha_w1 = (const float*)d_in[8];
    const float* alpha_w2 = (const float*)d_in[9];
    float* out = (float*)d_out;

    float *xct, *hm, *accum, *ps, *qsum, *rs, *wtq;
    __half *xch, *h1h, *hmh, *wth;
    cudaGetSymbolAddress((void**)&xct,   g_xct);
    cudaGetSymbolAddress((void**)&xch,   g_xch);
    cudaGetSymbolAddress((void**)&h1h,   g_h1h);
    cudaGetSymbolAddress((void**)&hm,    g_hm);
    cudaGetSymbolAddress((void**)&hmh,   g_hmh);
    cudaGetSymbolAddress((void**)&accum, g_accum);
    cudaGetSymbolAddress((void**)&ps,    g_ps);
    cudaGetSymbolAddress((void**)&qsum,  g_qsum);
    cudaGetSymbolAddress((void**)&rs,    g_rs);
    cudaGetSymbolAddress((void**)&wtq,   g_wtq);
    cudaGetSymbolAddress((void**)&wth,   g_wth);

    float* hs        = accum;                 // [MT]
    float* eta_sum   = accum + MT;            // [LL]
    float* alpha_sum = accum + MT + LL;       // [LL]
    float* ssA       = accum + MT + 2*LL;     // [MT]
    float* sgA       = accum + 2*MT + 2*LL;   // [MT]
    float* Pp = ps;
    float* Ss = ps + LL;

    static bool attr_done = false;
    if (!attr_done) {
        cudaFuncSetAttribute(gemm_q,     cudaFuncAttributeMaxDynamicSharedMemorySize, SMEM_GB);
        cudaFuncSetAttribute(gemm_h<1>,  cudaFuncAttributeMaxDynamicSharedMemorySize, SMEM_H);
        cudaFuncSetAttribute(gemm_h<2>,  cudaFuncAttributeMaxDynamicSharedMemorySize, SMEM_H);
        cudaFuncSetAttribute(gemm_h<3>,  cudaFuncAttributeMaxDynamicSharedMemorySize, SMEM_H);
        cudaFuncSetAttribute(gemm_h<4>,  cudaFuncAttributeMaxDynamicSharedMemorySize, SMEM_H);
        attr_done = true;
    }

    // 0) prep weights + zero accum (z==7)
    prep_weights<<<dim3(16, 16, 8), dim3(32, 8)>>>(eta_w1, alpha_w1, eta_w2, alpha_w2,
                                                   q_w, mem_w1, mem_w2, wtq, wth, accum);
    // 1) conv -> xct (tf32) + xch (fp16)
    conv_kernel<<<(MT * (DD/4) + 255) / 256, 256>>>(x, conv_w, conv_b, xct, xch);

    dim3 grid2(DD / 128, MT / 128, 2);
    dim3 grid1(DD / 128, MT / 128, 1);
    __half* wh0 = wth + 0LL * DD * DD;  // eta_w1^T
    __half* wh1 = wth + 1LL * DD * DD;  // alpha_w1^T
    __half* wh2 = wth + 2LL * DD * DD;  // eta_w2^T
    __half* wh3 = wth + 3LL * DD * DD;  // alpha_w2^T
    __half* wh4 = wth + 4LL * DD * DD;  // mem_w1^T
    __half* wh5 = wth + 5LL * DD * DD;  // mem_w2^T

    // 2) fp16: xch @ {eta_w1, alpha_w1} -> fp16 gelu -> h1h[z]
    gemm_h<1><<<grid2, 256, SMEM_H>>>(xch, SZ, wh0, wh1, h1h, h1h + SZ,
                                      nullptr, nullptr, nullptr, nullptr, nullptr, nullptr,
                                      nullptr, nullptr);
    // 3) tf32: xct @ q_w^T -> hm (f32) + hmh (fp16) + fused rownorm atomics
    gemm_q<<<grid1, 256, SMEM_GB>>>(xct, wtq, hm, hmh, ssA, sgA);
    // 4) fp16: h1h[z] @ {eta_w2, alpha_w2} -> sigmoid(xch + .) -> per-l sums
    gemm_h<2><<<grid2, 256, SMEM_H>>>(h1h, SZ, wh2, wh3, nullptr, nullptr,
                                      xch, nullptr, nullptr, nullptr, nullptr, nullptr,
                                      eta_sum, alpha_sum);
    // 5) scan (block 0) + rownorm finalize (blocks 1..16)
    scan_kernel<<<17, 1024>>>(eta_sum, ps, ssA, sgA, rs, qsum);
    // 6) fp16: hmh @ mem_w1, h = gelu(P*RS*acc + S*qsum) -> h1h[0] (fp16), hs atomics
    gemm_h<3><<<grid1, 256, SMEM_H>>>(hmh, 0LL, wh4, wh4, h1h, h1h,
                                      nullptr, nullptr, Pp, Ss, qsum, rs,
                                      hs, nullptr);
    // 7) fp16: h1h[0] @ mem_w2, out(f32) = RS*hm + P*acc + S*hs
    gemm_h<4><<<grid1, 256, SMEM_H>>>(h1h, 0LL, wh5, wh5, out, out,
                                      nullptr, hm, Pp, Ss, hs, rs,
                                      nullptr, nullptr);
}